// round 10
// baseline (speedup 1.0000x reference)
#include <cuda_runtime.h>
#include <cstdint>

// Problem constants
#define BATCH      32768
#define NFEAT      128
#define NTREES     4000
#define NINT       63
#define NLEAF      64
#define NCLS       10
#define LR         0.1f

// Main-kernel tiling: one CTA per SM; 224 samples, 448 threads (2 threads per
// sample, each owning half the stages of every chunk) -> 14 warps.
#define SPC        224
#define TPB        448
#define GRID       ((BATCH + SPC - 1) / SPC)   // 147

#define CHUNK_STAGES 8
#define CHUNK_TREES  (CHUNK_STAGES * NCLS)     // 80 trees per buffer
#define NCHUNK       (NTREES / CHUNK_TREES)    // 50

// Node word: ((f*SPC) << 16) | j  (prescaled feature offset + rank code)
#define NODE_CHUNK   (CHUNK_TREES * NINT)      // 5040 u32
#define NODE_BYTES   (NODE_CHUNK * 4)          // 20160
#define LEAF_CHUNK   (CHUNK_TREES * NLEAF)     // 5120 f32
#define LEAF_BYTES   (LEAF_CHUNK * 4)          // 20480
#define BUF_BYTES    (NODE_BYTES + LEAF_BYTES) // 40640

// x-code tile: FEATURE-MAJOR u32, xs[f*SPC + r]; 224 ≡ 0 (mod 32) -> bank = r.
#define XS_BYTES    (NFEAT * SPC * 4)          // 114688
#define BUF_OFF(b)  (XS_BYTES + (b) * BUF_BYTES)
#define MBAR_OFF    (XS_BYTES + 2 * BUF_BYTES) // 195968
#define SMEM_TOTAL  (MBAR_OFF + 16)            // 195984

#define SORTN 4096                              // per-feature sort size
#define FSEG  3072                              // per-feature segment capacity
#define PREP_SMEM (SORTN * 8 + SORTN * 4)       // 49152

// Scatter kernel shape
#define SCTAS   64
#define STPB    512
#define PER_TH  8                               // 64*512*8 = 262144 >= 252000
#define NELEMS  (NTREES * NINT)                 // 252000

// Device-global scratch (rebuilt deterministically every launch)
__device__ __align__(16) uint32_t g_nodesQ[NTREES * NINT];   // ((f*SPC)<<16)|j
__device__ uint16_t g_xcode[(size_t)NFEAT * BATCH];
__device__ int      g_fcount[NFEAT];
__device__ uint64_t g_tpair[(size_t)NFEAT * FSEG];           // (key<<32)|node_id

extern __shared__ char smem_raw[];

// Order-preserving float -> u32 key (monotone; caller canonicalizes -0).
__device__ __forceinline__ uint32_t fkey(float v) {
    int b = __float_as_int(v);
    return (uint32_t)(b ^ ((b >> 31) | 0x80000000));
}

__device__ __forceinline__ uint32_t s2u(const void* p) {
    uint32_t a;
    asm("{ .reg .u64 t; cvta.to.shared.u64 t, %1; cvt.u32.u64 %0, t; }"
        : "=r"(a) : "l"(p));
    return a;
}

__device__ __forceinline__ void mbar_init(uint32_t bar, uint32_t cnt) {
    asm volatile("mbarrier.init.shared.b64 [%0], %1;" :: "r"(bar), "r"(cnt) : "memory");
}

__device__ __forceinline__ void mbar_expect_tx(uint32_t bar, uint32_t bytes) {
    asm volatile("mbarrier.arrive.expect_tx.shared.b64 _, [%0], %1;"
                 :: "r"(bar), "r"(bytes) : "memory");
}

__device__ __forceinline__ void mbar_wait(uint32_t bar, uint32_t parity) {
    uint32_t done;
    asm volatile(
        "{\n\t.reg .pred p;\n\t"
        "mbarrier.try_wait.parity.acquire.cta.shared::cta.b64 p, [%1], %2;\n\t"
        "selp.b32 %0, 1, 0, p;\n\t}"
        : "=r"(done) : "r"(bar), "r"(parity) : "memory");
    while (!done) {
        asm volatile(
            "{\n\t.reg .pred p;\n\t"
            "mbarrier.try_wait.parity.acquire.cta.shared::cta.b64 p, [%1], %2, 0x989680;\n\t"
            "selp.b32 %0, 1, 0, p;\n\t}"
            : "=r"(done) : "r"(bar), "r"(parity) : "memory");
    }
}

__device__ __forceinline__ void bulk_g2s(uint32_t dst, const void* src,
                                         uint32_t bytes, uint32_t bar) {
    asm volatile(
        "cp.async.bulk.shared::cluster.global.mbarrier::complete_tx::bytes "
        "[%0], [%1], %2, [%3];"
        :: "r"(dst), "l"(src), "r"(bytes), "r"(bar) : "memory");
}

// ============================ prep kernels ============================

__global__ void prep_zero_kernel() {
    if (threadIdx.x < NFEAT) g_fcount[threadIdx.x] = 0;
}

// Smem-aggregated scatter: per-CTA histogram -> ONE global atomic per
// (CTA, feature) -> per-element smem offsets. Segment order is arbitrary
// (sorted afterwards), so cross-CTA atomic order doesn't matter.
__global__ void __launch_bounds__(STPB, 1)
prep_scatter_kernel(const int* __restrict__ features,
                    const float* __restrict__ thresholds)
{
    __shared__ int h[NFEAT];
    __shared__ int hbase[NFEAT];
    const int tid = threadIdx.x;

    for (int i = tid; i < NFEAT; i += STPB) h[i] = 0;
    __syncthreads();

    int      fv[PER_TH];
    uint32_t kv[PER_TH];
    const int base = blockIdx.x * (STPB * PER_TH);

    #pragma unroll
    for (int e = 0; e < PER_TH; e++) {
        int i = base + e * STPB + tid;
        fv[e] = -1;
        if (i < NELEMS) {
            fv[e] = features[i];
            kv[e] = fkey(thresholds[i] + 0.0f);   // canonicalize -0
            atomicAdd(&h[fv[e]], 1);
        }
    }
    __syncthreads();

    for (int i = tid; i < NFEAT; i += STPB) {
        hbase[i] = atomicAdd(&g_fcount[i], h[i]);
        h[i] = 0;
    }
    __syncthreads();

    #pragma unroll
    for (int e = 0; e < PER_TH; e++) {
        if (fv[e] >= 0) {
            int i   = base + e * STPB + tid;
            int off = hbase[fv[e]] + atomicAdd(&h[fv[e]], 1);
            g_tpair[(size_t)fv[e] * FSEG + off] =
                ((uint64_t)kv[e] << 32) | (uint32_t)i;
        }
    }
}

// Per-feature: bitonic-sort thresholds, emit node codes j = #{t <= thr} and
// sample codes c = #{t < x}. Exact: x > thr <=> c >= j.
__global__ void __launch_bounds__(1024, 1)
prep_feature_kernel(const float* __restrict__ x)
{
    extern __shared__ char sm4[];
    uint64_t* spair = reinterpret_cast<uint64_t*>(sm4);             // SORTN
    uint32_t* skey  = reinterpret_cast<uint32_t*>(sm4 + SORTN * 8); // SORTN

    const int f   = blockIdx.x;
    const int tid = threadIdx.x;
    const int m   = g_fcount[f];
    const uint64_t* seg = g_tpair + (size_t)f * FSEG;

    for (int p = tid; p < SORTN; p += 1024)
        spair[p] = (p < m) ? seg[p] : 0xFFFFFFFFFFFFFFFFull;
    __syncthreads();

    for (int k = 2; k <= SORTN; k <<= 1) {
        for (int jj = k >> 1; jj > 0; jj >>= 1) {
            for (int i = tid; i < SORTN; i += 1024) {
                int p = i ^ jj;
                if (p > i) {
                    uint64_t a = spair[i], b = spair[p];
                    bool up = ((i & k) == 0);
                    if ((a > b) == up) { spair[i] = b; spair[p] = a; }
                }
            }
            __syncthreads();
        }
    }

    for (int p = tid; p < SORTN; p += 1024)
        skey[p] = (uint32_t)(spair[p] >> 32);
    __syncthreads();

    // Node codes: j = upper_bound = #{t <= thr}; prescale f into the word.
    for (int p = tid; p < m; p += 1024) {
        uint32_t key = skey[p];
        uint32_t id  = (uint32_t)(spair[p] & 0xFFFFFFFFull);
        int pos = 0;
        #pragma unroll
        for (int w = SORTN >> 1; w >= 1; w >>= 1)
            if (skey[pos + w - 1] <= key) pos += w;
        g_nodesQ[id] = ((uint32_t)(f * SPC) << 16) | (uint32_t)pos;
    }

    // Sample codes: c = lower_bound = #{t < x}
    for (int s = tid; s < BATCH; s += 1024) {
        float v = x[(size_t)s * NFEAT + f] + 0.0f;
        uint32_t key = fkey(v);
        int pos = 0;
        #pragma unroll
        for (int w = SORTN >> 1; w >= 1; w >>= 1)
            if (skey[pos + w - 1] < key) pos += w;
        g_xcode[(size_t)f * BATCH + s] = (uint16_t)pos;
    }
}

// ============================ main kernel ============================

__global__ void __launch_bounds__(TPB, 1)
gbt_forest_kernel(const float* __restrict__ leaf_values,
                  const float* __restrict__ init_out,
                  float*       __restrict__ out)
{
    uint32_t* xsw = reinterpret_cast<uint32_t*>(smem_raw);
    uint64_t* mbar = reinterpret_cast<uint64_t*>(smem_raw + MBAR_OFF);

    const int tid  = threadIdx.x;
    const int half = tid >= SPC;          // 0: stages 0-3, 1: stages 4-7
    const int r    = tid - half * SPC;    // sample slot 0..223
    const int base = blockIdx.x * SPC;

    const uint32_t bar0 = s2u(&mbar[0]);
    const uint32_t bar1 = s2u(&mbar[1]);
    const uint32_t dst0 = s2u(smem_raw + BUF_OFF(0));
    const uint32_t dst1 = s2u(smem_raw + BUF_OFF(1));

    const uint32_t* gN = g_nodesQ;

    if (tid == 0) {
        mbar_init(bar0, 1);
        mbar_init(bar1, 1);
        asm volatile("fence.proxy.async.shared::cta;" ::: "memory");
        mbar_expect_tx(bar0, BUF_BYTES);
        bulk_g2s(dst0,              gN,                       NODE_BYTES, bar0);
        bulk_g2s(dst0 + NODE_BYTES, leaf_values,              LEAF_BYTES, bar0);
        mbar_expect_tx(bar1, BUF_BYTES);
        bulk_g2s(dst1,              gN + NODE_CHUNK,          NODE_BYTES, bar1);
        bulk_g2s(dst1 + NODE_BYTES, leaf_values + LEAF_CHUNK, LEAF_BYTES, bar1);
    }

    // Stage x-code tile (u16 global -> u32 smem, feature-major, conflict-free)
    for (int ii = tid; ii < NFEAT * SPC; ii += TPB) {
        int f  = ii / SPC;
        int rr = ii - f * SPC;
        int gs = min(base + rr, BATCH - 1);
        xsw[f * SPC + rr] = g_xcode[(size_t)f * BATCH + gs];
    }
    __syncthreads();

    float acc[NCLS];
    #pragma unroll
    for (int k = 0; k < NCLS; k++) acc[k] = 0.0f;

    const uint32_t* xcol = xsw + r;
    const int sgBase = half * 4;

    uint32_t barCur = bar0, barNxt = bar1;
    uint32_t dstCur = dst0, dstNxt = dst1;
    const char* pCur = smem_raw + BUF_OFF(0);
    const char* pNxt = smem_raw + BUF_OFF(1);
    int phCur = 0, phNxt = 0;

    for (int c = 0; c < NCHUNK; c++) {
        mbar_wait(barCur, phCur);
        phCur ^= 1;

        const uint32_t* nodeB = reinterpret_cast<const uint32_t*>(pCur);
        const float*    leafB = reinterpret_cast<const float*>(pCur + NODE_BYTES);

        #pragma unroll
        for (int s = 0; s < 4; s++) {
            const int sg = sgBase + s;
            #pragma unroll
            for (int k = 0; k < NCLS; k++) {
                const int j = sg * NCLS + k;
                const uint32_t* nt = nodeB + j * NINT;
                uint32_t idx = 0;
                #pragma unroll
                for (int l = 0; l < 6; l++) {
                    uint32_t nw = nt[idx];        // 1 wf (<=32-consecutive window)
                    uint32_t cd = xcol[nw >> 16]; // 1 wf (bank = lane), no IMAD
                    idx = 2 * idx + 1 + (cd >= (nw & 0xFFFFu));   // branchless
                }
                acc[k] += leafB[j * NLEAF + ((int)idx - NINT)];   // single LDS.32
            }
        }

        __syncthreads();
        if (c + 2 < NCHUNK && tid == 0) {
            const int nc = c + 2;
            mbar_expect_tx(barCur, BUF_BYTES);
            bulk_g2s(dstCur,              gN + (size_t)nc * NODE_CHUNK, NODE_BYTES, barCur);
            bulk_g2s(dstCur + NODE_BYTES, leaf_values + (size_t)nc * LEAF_CHUNK,
                     LEAF_BYTES, barCur);
        }

        uint32_t tb = barCur; barCur = barNxt; barNxt = tb;
        uint32_t td = dstCur; dstCur = dstNxt; dstNxt = td;
        const char* tp = pCur; pCur = pNxt; pNxt = tp;
        int tph = phCur; phCur = phNxt; phNxt = tph;
    }

    // Cross-half reduction (reuse x tile region)
    float* red = reinterpret_cast<float*>(smem_raw);
    if (half == 1) {
        #pragma unroll
        for (int k = 0; k < NCLS; k++) red[r * NCLS + k] = acc[k];
    }
    __syncthreads();

    if (half == 0 && base + r < BATCH) {
        const int sample = base + r;
        #pragma unroll
        for (int k = 0; k < NCLS; k++) {
            out[(size_t)sample * NCLS + k] =
                __ldg(init_out + k) + LR * (acc[k] + red[r * NCLS + k]);
        }
    }
}

extern "C" void kernel_launch(void* const* d_in, const int* in_sizes, int n_in,
                              void* d_out, int out_size)
{
    (void)in_sizes; (void)n_in; (void)out_size;

    const float* x           = (const float*)d_in[0];
    const int*   features    = (const int*)  d_in[1];
    const float* thresholds  = (const float*)d_in[2];
    const float* leaf_values = (const float*)d_in[3];
    const float* init_out    = (const float*)d_in[4];
    float*       out         = (float*)d_out;

    static bool attr_set = false;
    if (!attr_set) {
        cudaFuncSetAttribute(gbt_forest_kernel,
                             cudaFuncAttributeMaxDynamicSharedMemorySize, SMEM_TOTAL);
        cudaFuncSetAttribute(prep_feature_kernel,
                             cudaFuncAttributeMaxDynamicSharedMemorySize, PREP_SMEM);
        attr_set = true;
    }

    prep_zero_kernel<<<1, NFEAT>>>();
    prep_scatter_kernel<<<SCTAS, STPB>>>(features, thresholds);
    prep_feature_kernel<<<NFEAT, 1024, PREP_SMEM>>>(x);
    gbt_forest_kernel<<<GRID, TPB, SMEM_TOTAL>>>(leaf_values, init_out, out);
}

// round 11
// speedup vs baseline: 1.1140x; 1.1140x over previous
#include <cuda_runtime.h>
#include <cstdint>

// Problem constants
#define BATCH      32768
#define NFEAT      128
#define NTREES     4000
#define NINT       63
#define NLEAF      64
#define NCLS       10
#define LR         0.1f

// Main-kernel tiling: one CTA per SM; 224 samples, 448 threads (2 threads per
// sample, each owning half the stages of every chunk) -> 14 warps.
#define SPC        224
#define TPB        448
#define GRID       ((BATCH + SPC - 1) / SPC)   // 147

#define CHUNK_STAGES 8
#define CHUNK_TREES  (CHUNK_STAGES * NCLS)     // 80 trees per buffer
#define NCHUNK       (NTREES / CHUNK_TREES)    // 50

// Node word: ((f*SPC) << 12) | j   (word-offset prefix + 12-bit rank code)
// x-code word: ((f*SPC) << 12) | c -> equal prefixes => (cd >= nw) <=> (c >= j)
#define NODE_CHUNK   (CHUNK_TREES * NINT)      // 5040 u32
#define NODE_BYTES   (NODE_CHUNK * 4)          // 20160
#define LEAF_CHUNK   (CHUNK_TREES * NLEAF)     // 5120 f32
#define LEAF_BYTES   (LEAF_CHUNK * 4)          // 20480
#define BUF_BYTES    (NODE_BYTES + LEAF_BYTES) // 40640

// x-code tile: FEATURE-MAJOR u32, xs[f*SPC + r]; 224 ≡ 0 (mod 32) -> bank = r.
#define XS_BYTES    (NFEAT * SPC * 4)          // 114688
#define BUF_OFF(b)  (XS_BYTES + (b) * BUF_BYTES)
#define MBAR_OFF    (XS_BYTES + 2 * BUF_BYTES) // 195968
#define SMEM_TOTAL  (MBAR_OFF + 16)            // 195984

#define SORTN 4096
#define FSEG  3072
// prep_feature smem: skey u32[4096] (16KB) + replicated 8-level tree (255*32 u32, 32640B)
#define REP_NODES 255
#define PREP_SMEM (SORTN * 4 + REP_NODES * 32 * 4)   // 48,976

// Scatter kernel shape
#define SCTAS   64
#define STPB    512
#define PER_TH  8
#define NELEMS  (NTREES * NINT)                 // 252000

// Device-global scratch (rebuilt deterministically every launch)
__device__ __align__(16) uint32_t g_nodesQ[NTREES * NINT];   // ((f*SPC)<<12)|j
__device__ __align__(16) uint32_t g_xcode[(size_t)NFEAT * BATCH]; // ((f*SPC)<<12)|c
__device__ int      g_fcount[NFEAT];
__device__ uint64_t g_tpair[(size_t)NFEAT * FSEG];           // (key<<32)|node_id
__device__ float    g_xT[(size_t)NFEAT * BATCH];             // transposed x

extern __shared__ char smem_raw[];

// Order-preserving float -> u32 key (monotone; caller canonicalizes -0 via +0.0f).
__device__ __forceinline__ uint32_t fkey(float v) {
    int b = __float_as_int(v);
    return (uint32_t)(b ^ ((b >> 31) | 0x80000000));
}

__device__ __forceinline__ uint32_t s2u(const void* p) {
    uint32_t a;
    asm("{ .reg .u64 t; cvta.to.shared.u64 t, %1; cvt.u32.u64 %0, t; }"
        : "=r"(a) : "l"(p));
    return a;
}

__device__ __forceinline__ void mbar_init(uint32_t bar, uint32_t cnt) {
    asm volatile("mbarrier.init.shared.b64 [%0], %1;" :: "r"(bar), "r"(cnt) : "memory");
}

__device__ __forceinline__ void mbar_expect_tx(uint32_t bar, uint32_t bytes) {
    asm volatile("mbarrier.arrive.expect_tx.shared.b64 _, [%0], %1;"
                 :: "r"(bar), "r"(bytes) : "memory");
}

__device__ __forceinline__ void mbar_wait(uint32_t bar, uint32_t parity) {
    uint32_t done;
    asm volatile(
        "{\n\t.reg .pred p;\n\t"
        "mbarrier.try_wait.parity.acquire.cta.shared::cta.b64 p, [%1], %2;\n\t"
        "selp.b32 %0, 1, 0, p;\n\t}"
        : "=r"(done) : "r"(bar), "r"(parity) : "memory");
    while (!done) {
        asm volatile(
            "{\n\t.reg .pred p;\n\t"
            "mbarrier.try_wait.parity.acquire.cta.shared::cta.b64 p, [%1], %2, 0x989680;\n\t"
            "selp.b32 %0, 1, 0, p;\n\t}"
            : "=r"(done) : "r"(bar), "r"(parity) : "memory");
    }
}

__device__ __forceinline__ void bulk_g2s(uint32_t dst, const void* src,
                                         uint32_t bytes, uint32_t bar) {
    asm volatile(
        "cp.async.bulk.shared::cluster.global.mbarrier::complete_tx::bytes "
        "[%0], [%1], %2, [%3];"
        :: "r"(dst), "l"(src), "r"(bytes), "r"(bar) : "memory");
}

// ============================ prep kernels ============================

__global__ void prep_zero_kernel() {
    if (threadIdx.x < NFEAT) g_fcount[threadIdx.x] = 0;
}

// Smem-aggregated scatter: ONE global atomic per (CTA, feature).
__global__ void __launch_bounds__(STPB, 1)
prep_scatter_kernel(const int* __restrict__ features,
                    const float* __restrict__ thresholds)
{
    __shared__ int h[NFEAT];
    __shared__ int hbase[NFEAT];
    const int tid = threadIdx.x;

    for (int i = tid; i < NFEAT; i += STPB) h[i] = 0;
    __syncthreads();

    int      fv[PER_TH];
    uint32_t kv[PER_TH];
    const int base = blockIdx.x * (STPB * PER_TH);

    #pragma unroll
    for (int e = 0; e < PER_TH; e++) {
        int i = base + e * STPB + tid;
        fv[e] = -1;
        if (i < NELEMS) {
            fv[e] = features[i];
            kv[e] = fkey(thresholds[i] + 0.0f);
            atomicAdd(&h[fv[e]], 1);
        }
    }
    __syncthreads();

    for (int i = tid; i < NFEAT; i += STPB) {
        hbase[i] = atomicAdd(&g_fcount[i], h[i]);
        h[i] = 0;
    }
    __syncthreads();

    #pragma unroll
    for (int e = 0; e < PER_TH; e++) {
        if (fv[e] >= 0) {
            int i   = base + e * STPB + tid;
            int off = hbase[fv[e]] + atomicAdd(&h[fv[e]], 1);
            g_tpair[(size_t)fv[e] * FSEG + off] =
                ((uint64_t)kv[e] << 32) | (uint32_t)i;
        }
    }
}

// Transpose x [BATCH, NFEAT] -> g_xT [NFEAT, BATCH] so prep_feature reads
// feature columns coalesced. 32x32 tiles.
__global__ void __launch_bounds__(256, 2)
prep_transpose_kernel(const float* __restrict__ x)
{
    __shared__ float t[32][33];
    const int tx = threadIdx.x;        // 0..31
    const int ty = threadIdx.y;        // 0..7
    const int sBase = blockIdx.x * 32;
    const int fBase = blockIdx.y * 32;

    #pragma unroll
    for (int rr = ty; rr < 32; rr += 8)
        t[rr][tx] = x[(size_t)(sBase + rr) * NFEAT + fBase + tx];
    __syncthreads();
    #pragma unroll
    for (int rr = ty; rr < 32; rr += 8)
        g_xT[(size_t)(fBase + rr) * BATCH + sBase + tx] = t[tx][rr];
}

// Per-feature: sort u32 keys (bitonic), node codes via <=-search, then a
// bank-replicated 8-level top tree accelerates the 32768 sample searches.
__global__ void __launch_bounds__(1024, 1)
prep_feature_kernel()
{
    extern __shared__ char sm4[];
    uint32_t* skey = reinterpret_cast<uint32_t*>(sm4);              // 4096
    uint32_t* rep  = reinterpret_cast<uint32_t*>(sm4 + SORTN * 4);  // 255*32

    const int f    = blockIdx.x;
    const int tid  = threadIdx.x;
    const int lane = tid & 31;
    const int m    = g_fcount[f];
    const uint64_t* seg = g_tpair + (size_t)f * FSEG;
    const uint32_t prefix = (uint32_t)(f * SPC) << 12;

    for (int p = tid; p < SORTN; p += 1024)
        skey[p] = (p < m) ? (uint32_t)(seg[p] >> 32) : 0xFFFFFFFFu;
    __syncthreads();

    // Bitonic sort u32 ascending
    for (int k = 2; k <= SORTN; k <<= 1) {
        for (int jj = k >> 1; jj > 0; jj >>= 1) {
            for (int i = tid; i < SORTN; i += 1024) {
                int p = i ^ jj;
                if (p > i) {
                    uint32_t a = skey[i], b = skey[p];
                    bool up = ((i & k) == 0);
                    if ((a > b) == up) { skey[i] = b; skey[p] = a; }
                }
            }
            __syncthreads();
        }
    }

    // Node codes: j = upper_bound (<=); write ((f*SPC)<<12)|j
    for (int p = tid; p < m; p += 1024) {
        uint64_t pr  = seg[p];
        uint32_t key = (uint32_t)(pr >> 32);
        uint32_t id  = (uint32_t)(pr & 0xFFFFFFFFull);
        int pos = 0;
        #pragma unroll
        for (int w = SORTN >> 1; w >= 1; w >>= 1)
            if (skey[pos + w - 1] <= key) pos += w;
        g_nodesQ[id] = prefix | (uint32_t)pos;
    }
    __syncthreads();

    // Build bank-replicated top tree: rep[nb*32 + lane] = skey[(2q+1)*w - 1]
    for (int i = tid; i < REP_NODES * 32; i += 1024) {
        int nb = i >> 5;
        int L  = 31 - __clz(nb + 1);
        int q  = (nb + 1) - (1 << L);
        int w  = 2048 >> L;
        rep[i] = skey[(2 * q + 1) * w - 1];
    }
    __syncthreads();

    // Sample codes: c = lower_bound (<). First 8 levels via replicated tree
    // (bank = lane -> conflict-free), last 4 via skey.
    for (int s = tid; s < BATCH; s += 1024) {
        uint32_t key = fkey(g_xT[(size_t)f * BATCH + s] + 0.0f);
        int q = 0;
        #pragma unroll
        for (int L = 0; L < 8; L++) {
            uint32_t tk = rep[(((1 << L) - 1 + q) << 5) + lane];
            q = 2 * q + (tk < key);
        }
        int pos = q << 4;
        if (skey[pos + 7] < key) pos += 8;
        if (skey[pos + 3] < key) pos += 4;
        if (skey[pos + 1] < key) pos += 2;
        if (skey[pos]     < key) pos += 1;
        g_xcode[(size_t)f * BATCH + s] = prefix | (uint32_t)pos;
    }
}

// ============================ main kernel ============================

__global__ void __launch_bounds__(TPB, 1)
gbt_forest_kernel(const float* __restrict__ leaf_values,
                  const float* __restrict__ init_out,
                  float*       __restrict__ out)
{
    uint32_t* xsw = reinterpret_cast<uint32_t*>(smem_raw);
    uint64_t* mbar = reinterpret_cast<uint64_t*>(smem_raw + MBAR_OFF);

    const int tid  = threadIdx.x;
    const int half = tid >= SPC;          // 0: stages 0-3, 1: stages 4-7
    const int r    = tid - half * SPC;    // sample slot 0..223
    const int base = blockIdx.x * SPC;

    const uint32_t bar0 = s2u(&mbar[0]);
    const uint32_t bar1 = s2u(&mbar[1]);
    const uint32_t dst0 = s2u(smem_raw + BUF_OFF(0));
    const uint32_t dst1 = s2u(smem_raw + BUF_OFF(1));

    const uint32_t* gN = g_nodesQ;

    if (tid == 0) {
        mbar_init(bar0, 1);
        mbar_init(bar1, 1);
        asm volatile("fence.proxy.async.shared::cta;" ::: "memory");
        mbar_expect_tx(bar0, BUF_BYTES);
        bulk_g2s(dst0,              gN,                       NODE_BYTES, bar0);
        bulk_g2s(dst0 + NODE_BYTES, leaf_values,              LEAF_BYTES, bar0);
        mbar_expect_tx(bar1, BUF_BYTES);
        bulk_g2s(dst1,              gN + NODE_CHUNK,          NODE_BYTES, bar1);
        bulk_g2s(dst1 + NODE_BYTES, leaf_values + LEAF_CHUNK, LEAF_BYTES, bar1);
    }

    // Stage x-code tile (u32 global -> u32 smem, feature-major, conflict-free)
    for (int ii = tid; ii < NFEAT * SPC; ii += TPB) {
        int ff = ii / SPC;
        int rr = ii - ff * SPC;
        int gs = min(base + rr, BATCH - 1);
        xsw[ff * SPC + rr] = g_xcode[(size_t)ff * BATCH + gs];
    }
    __syncthreads();

    float acc[NCLS];
    #pragma unroll
    for (int k = 0; k < NCLS; k++) acc[k] = 0.0f;

    const uint32_t* xcol = xsw + r;
    const int sgBase = half * 4;

    uint32_t barCur = bar0, barNxt = bar1;
    uint32_t dstCur = dst0, dstNxt = dst1;
    const char* pCur = smem_raw + BUF_OFF(0);
    const char* pNxt = smem_raw + BUF_OFF(1);
    int phCur = 0, phNxt = 0;

    for (int c = 0; c < NCHUNK; c++) {
        mbar_wait(barCur, phCur);
        phCur ^= 1;

        const uint32_t* nodeB = reinterpret_cast<const uint32_t*>(pCur);
        const float*    leafB = reinterpret_cast<const float*>(pCur + NODE_BYTES);

        #pragma unroll
        for (int s = 0; s < 4; s++) {
            const int sg = sgBase + s;
            #pragma unroll
            for (int k = 0; k < NCLS; k++) {
                const int tj = sg * NCLS + k;
                const uint32_t* nt = nodeB + tj * NINT;
                uint32_t idx = 0;
                #pragma unroll
                for (int l = 0; l < 6; l++) {
                    uint32_t nw = nt[idx];        // 1 wf
                    uint32_t cd = xcol[nw >> 12]; // 1 wf (bank = lane)
                    idx = 2 * idx + 1 + (cd >= nw);  // prefix-equal compare, no AND
                }
                acc[k] += leafB[tj * NLEAF + ((int)idx - NINT)];
            }
        }

        __syncthreads();
        if (c + 2 < NCHUNK && tid == 0) {
            const int nc = c + 2;
            mbar_expect_tx(barCur, BUF_BYTES);
            bulk_g2s(dstCur,              gN + (size_t)nc * NODE_CHUNK, NODE_BYTES, barCur);
            bulk_g2s(dstCur + NODE_BYTES, leaf_values + (size_t)nc * LEAF_CHUNK,
                     LEAF_BYTES, barCur);
        }

        uint32_t tb = barCur; barCur = barNxt; barNxt = tb;
        uint32_t td = dstCur; dstCur = dstNxt; dstNxt = td;
        const char* tp = pCur; pCur = pNxt; pNxt = tp;
        int tph = phCur; phCur = phNxt; phNxt = tph;
    }

    // Cross-half reduction (reuse x tile region)
    float* red = reinterpret_cast<float*>(smem_raw);
    if (half == 1) {
        #pragma unroll
        for (int k = 0; k < NCLS; k++) red[r * NCLS + k] = acc[k];
    }
    __syncthreads();

    if (half == 0 && base + r < BATCH) {
        const int sample = base + r;
        #pragma unroll
        for (int k = 0; k < NCLS; k++) {
            out[(size_t)sample * NCLS + k] =
                __ldg(init_out + k) + LR * (acc[k] + red[r * NCLS + k]);
        }
    }
}

extern "C" void kernel_launch(void* const* d_in, const int* in_sizes, int n_in,
                              void* d_out, int out_size)
{
    (void)in_sizes; (void)n_in; (void)out_size;

    const float* x           = (const float*)d_in[0];
    const int*   features    = (const int*)  d_in[1];
    const float* thresholds  = (const float*)d_in[2];
    const float* leaf_values = (const float*)d_in[3];
    const float* init_out    = (const float*)d_in[4];
    float*       out         = (float*)d_out;

    static bool attr_set = false;
    if (!attr_set) {
        cudaFuncSetAttribute(gbt_forest_kernel,
                             cudaFuncAttributeMaxDynamicSharedMemorySize, SMEM_TOTAL);
        cudaFuncSetAttribute(prep_feature_kernel,
                             cudaFuncAttributeMaxDynamicSharedMemorySize, PREP_SMEM);
        attr_set = true;
    }

    prep_zero_kernel<<<1, NFEAT>>>();
    prep_scatter_kernel<<<SCTAS, STPB>>>(features, thresholds);
    {
        dim3 tb(32, 8);
        dim3 tg(BATCH / 32, NFEAT / 32);
        prep_transpose_kernel<<<tg, tb>>>(x);
    }
    prep_feature_kernel<<<NFEAT, 1024, PREP_SMEM>>>();
    gbt_forest_kernel<<<GRID, TPB, SMEM_TOTAL>>>(leaf_values, init_out, out);
}

// round 12
// speedup vs baseline: 1.3384x; 1.2015x over previous
#include <cuda_runtime.h>
#include <cstdint>

// Problem constants
#define BATCH      32768
#define NFEAT      128
#define NTREES     4000
#define NINT       63
#define NLEAF      64
#define NCLS       10
#define LR         0.1f

// Main-kernel tiling: TWO CTAs per SM. 112 samples/CTA, 448 threads =
// 4 threads per sample (each owns 1 stage of every 4-stage chunk) -> 14 warps
// per CTA, 28 per SM (7/SMSP) for latency hiding.
#define SPC        112
#define TPB        448
#define GRID       ((BATCH + SPC - 1) / SPC)   // 293 (~99% of 296 slots)

#define CHUNK_STAGES 4
#define CHUNK_TREES  (CHUNK_STAGES * NCLS)     // 40 trees per buffer
#define NCHUNK       (NTREES / CHUNK_TREES)    // 100

// Node word: ((f*SPC) << 12) | j ; x-code word: ((f*SPC) << 12) | c
// equal prefixes => (cd >= nw) <=> (c >= j)   (j,c < 4096)
#define NODE_CHUNK   (CHUNK_TREES * NINT)      // 2520 u32
#define NODE_BYTES   (NODE_CHUNK * 4)          // 10080 (16B multiple)
#define LEAF_CHUNK   (CHUNK_TREES * NLEAF)     // 2560 f32
#define LEAF_BYTES   (LEAF_CHUNK * 4)          // 10240
#define BUF_BYTES    (NODE_BYTES + LEAF_BYTES) // 20320

// x-code tile: FEATURE-MAJOR u32, xs[f*SPC + r]; 112 ≡ 16 (mod 32): within a
// warp lanes have distinct r mod 32 -> conflict-free (mixed warps ~2-way).
#define XS_BYTES    (NFEAT * SPC * 4)          // 57344
#define BUF_OFF(b)  (XS_BYTES + (b) * BUF_BYTES)
#define MBAR_OFF    (XS_BYTES + 2 * BUF_BYTES) // 97984
#define SMEM_TOTAL  (MBAR_OFF + 16)            // 98000  (x2 = 196000 <= carveout)

#define SORTN 4096
#define FSEG  3072
#define REP_NODES 255
#define SORT_SMEM  (SORTN * 4)                          // 16384
#define XCODE_SMEM (SORTN * 4 + REP_NODES * 32 * 4)     // 48976
#define XCODE_SPLIT 4                                    // CTAs per feature
#define XCODE_SAMP  (BATCH / XCODE_SPLIT)                // 8192

// Scatter kernel shape
#define SCTAS   64
#define STPB    512
#define PER_TH  8
#define NELEMS  (NTREES * NINT)                 // 252000

// Device-global scratch (rebuilt deterministically every launch)
__device__ __align__(16) uint32_t g_nodesQ[NTREES * NINT];        // ((f*SPC)<<12)|j
__device__ __align__(16) uint32_t g_xcode[(size_t)NFEAT * BATCH]; // ((f*SPC)<<12)|c
__device__ __align__(16) uint32_t g_skey[(size_t)NFEAT * SORTN];  // sorted keys
__device__ int      g_fcount[NFEAT];
__device__ uint64_t g_tpair[(size_t)NFEAT * FSEG];                // (key<<32)|node_id

extern __shared__ char smem_raw[];

// Order-preserving float -> u32 key (monotone; caller canonicalizes -0).
__device__ __forceinline__ uint32_t fkey(float v) {
    int b = __float_as_int(v);
    return (uint32_t)(b ^ ((b >> 31) | 0x80000000));
}

__device__ __forceinline__ uint32_t s2u(const void* p) {
    uint32_t a;
    asm("{ .reg .u64 t; cvta.to.shared.u64 t, %1; cvt.u32.u64 %0, t; }"
        : "=r"(a) : "l"(p));
    return a;
}

__device__ __forceinline__ void mbar_init(uint32_t bar, uint32_t cnt) {
    asm volatile("mbarrier.init.shared.b64 [%0], %1;" :: "r"(bar), "r"(cnt) : "memory");
}

__device__ __forceinline__ void mbar_expect_tx(uint32_t bar, uint32_t bytes) {
    asm volatile("mbarrier.arrive.expect_tx.shared.b64 _, [%0], %1;"
                 :: "r"(bar), "r"(bytes) : "memory");
}

__device__ __forceinline__ void mbar_wait(uint32_t bar, uint32_t parity) {
    uint32_t done;
    asm volatile(
        "{\n\t.reg .pred p;\n\t"
        "mbarrier.try_wait.parity.acquire.cta.shared::cta.b64 p, [%1], %2;\n\t"
        "selp.b32 %0, 1, 0, p;\n\t}"
        : "=r"(done) : "r"(bar), "r"(parity) : "memory");
    while (!done) {
        asm volatile(
            "{\n\t.reg .pred p;\n\t"
            "mbarrier.try_wait.parity.acquire.cta.shared::cta.b64 p, [%1], %2, 0x989680;\n\t"
            "selp.b32 %0, 1, 0, p;\n\t}"
            : "=r"(done) : "r"(bar), "r"(parity) : "memory");
    }
}

__device__ __forceinline__ void bulk_g2s(uint32_t dst, const void* src,
                                         uint32_t bytes, uint32_t bar) {
    asm volatile(
        "cp.async.bulk.shared::cluster.global.mbarrier::complete_tx::bytes "
        "[%0], [%1], %2, [%3];"
        :: "r"(dst), "l"(src), "r"(bytes), "r"(bar) : "memory");
}

// ============================ prep kernels ============================

__global__ void prep_zero_kernel() {
    if (threadIdx.x < NFEAT) g_fcount[threadIdx.x] = 0;
}

// Smem-aggregated scatter: ONE global atomic per (CTA, feature).
__global__ void __launch_bounds__(STPB, 1)
prep_scatter_kernel(const int* __restrict__ features,
                    const float* __restrict__ thresholds)
{
    __shared__ int h[NFEAT];
    __shared__ int hbase[NFEAT];
    const int tid = threadIdx.x;

    for (int i = tid; i < NFEAT; i += STPB) h[i] = 0;
    __syncthreads();

    int      fv[PER_TH];
    uint32_t kv[PER_TH];
    const int base = blockIdx.x * (STPB * PER_TH);

    #pragma unroll
    for (int e = 0; e < PER_TH; e++) {
        int i = base + e * STPB + tid;
        fv[e] = -1;
        if (i < NELEMS) {
            fv[e] = features[i];
            kv[e] = fkey(thresholds[i] + 0.0f);
            atomicAdd(&h[fv[e]], 1);
        }
    }
    __syncthreads();

    for (int i = tid; i < NFEAT; i += STPB) {
        hbase[i] = atomicAdd(&g_fcount[i], h[i]);
        h[i] = 0;
    }
    __syncthreads();

    #pragma unroll
    for (int e = 0; e < PER_TH; e++) {
        if (fv[e] >= 0) {
            int i   = base + e * STPB + tid;
            int off = hbase[fv[e]] + atomicAdd(&h[fv[e]], 1);
            g_tpair[(size_t)fv[e] * FSEG + off] =
                ((uint64_t)kv[e] << 32) | (uint32_t)i;
        }
    }
}

// Per-feature: bitonic-sort keys, emit node codes, write sorted keys to global.
__global__ void __launch_bounds__(1024, 1)
prep_sort_kernel()
{
    extern __shared__ char sm4[];
    uint32_t* skey = reinterpret_cast<uint32_t*>(sm4);   // 4096

    const int f   = blockIdx.x;
    const int tid = threadIdx.x;
    const int m   = g_fcount[f];
    const uint64_t* seg = g_tpair + (size_t)f * FSEG;
    const uint32_t prefix = (uint32_t)(f * SPC) << 12;

    for (int p = tid; p < SORTN; p += 1024)
        skey[p] = (p < m) ? (uint32_t)(seg[p] >> 32) : 0xFFFFFFFFu;
    __syncthreads();

    for (int k = 2; k <= SORTN; k <<= 1) {
        for (int jj = k >> 1; jj > 0; jj >>= 1) {
            for (int i = tid; i < SORTN; i += 1024) {
                int p = i ^ jj;
                if (p > i) {
                    uint32_t a = skey[i], b = skey[p];
                    bool up = ((i & k) == 0);
                    if ((a > b) == up) { skey[i] = b; skey[p] = a; }
                }
            }
            __syncthreads();
        }
    }

    // Node codes: j = upper_bound (<=)
    for (int p = tid; p < m; p += 1024) {
        uint64_t pr  = seg[p];
        uint32_t key = (uint32_t)(pr >> 32);
        uint32_t id  = (uint32_t)(pr & 0xFFFFFFFFull);
        int pos = 0;
        #pragma unroll
        for (int w = SORTN >> 1; w >= 1; w >>= 1)
            if (skey[pos + w - 1] <= key) pos += w;
        g_nodesQ[id] = prefix | (uint32_t)pos;
    }

    // Publish sorted keys for the xcode kernel
    for (int p = tid; p < SORTN; p += 1024)
        g_skey[(size_t)f * SORTN + p] = skey[p];
}

// 4 CTAs per feature: rebuild replicated top tree, search 8192 samples each.
__global__ void __launch_bounds__(1024, 1)
prep_xcode_kernel(const float* __restrict__ x)
{
    extern __shared__ char sm4[];
    uint32_t* skey = reinterpret_cast<uint32_t*>(sm4);              // 4096
    uint32_t* rep  = reinterpret_cast<uint32_t*>(sm4 + SORTN * 4);  // 255*32

    const int f    = blockIdx.x >> 2;
    const int part = blockIdx.x & 3;
    const int tid  = threadIdx.x;
    const int lane = tid & 31;
    const uint32_t prefix = (uint32_t)(f * SPC) << 12;

    for (int p = tid; p < SORTN; p += 1024)
        skey[p] = g_skey[(size_t)f * SORTN + p];
    __syncthreads();

    // Bank-replicated top tree: rep[nb*32 + lane] = skey[(2q+1)*w - 1]
    for (int i = tid; i < REP_NODES * 32; i += 1024) {
        int nb = i >> 5;
        int L  = 31 - __clz(nb + 1);
        int q  = (nb + 1) - (1 << L);
        int w  = 2048 >> L;
        rep[i] = skey[(2 * q + 1) * w - 1];
    }
    __syncthreads();

    const int sBase = part * XCODE_SAMP;
    for (int s = sBase + tid; s < sBase + XCODE_SAMP; s += 1024) {
        uint32_t key = fkey(x[(size_t)s * NFEAT + f] + 0.0f);
        int q = 0;
        #pragma unroll
        for (int L = 0; L < 8; L++) {
            uint32_t tk = rep[(((1 << L) - 1 + q) << 5) + lane];
            q = 2 * q + (tk < key);
        }
        int pos = q << 4;
        if (skey[pos + 7] < key) pos += 8;
        if (skey[pos + 3] < key) pos += 4;
        if (skey[pos + 1] < key) pos += 2;
        if (skey[pos]     < key) pos += 1;
        g_xcode[(size_t)f * BATCH + s] = prefix | (uint32_t)pos;
    }
}

// ============================ main kernel ============================

__global__ void __launch_bounds__(TPB, 2)
gbt_forest_kernel(const float* __restrict__ leaf_values,
                  const float* __restrict__ init_out,
                  float*       __restrict__ out)
{
    uint32_t* xsw = reinterpret_cast<uint32_t*>(smem_raw);
    uint64_t* mbar = reinterpret_cast<uint64_t*>(smem_raw + MBAR_OFF);

    const int tid = threadIdx.x;
    const int q   = tid / SPC;            // stage quarter 0..3
    const int r   = tid - q * SPC;        // sample slot 0..111
    const int base = blockIdx.x * SPC;

    const uint32_t bar0 = s2u(&mbar[0]);
    const uint32_t bar1 = s2u(&mbar[1]);
    const uint32_t dst0 = s2u(smem_raw + BUF_OFF(0));
    const uint32_t dst1 = s2u(smem_raw + BUF_OFF(1));

    const uint32_t* gN = g_nodesQ;

    if (tid == 0) {
        mbar_init(bar0, 1);
        mbar_init(bar1, 1);
        asm volatile("fence.proxy.async.shared::cta;" ::: "memory");
        mbar_expect_tx(bar0, BUF_BYTES);
        bulk_g2s(dst0,              gN,                       NODE_BYTES, bar0);
        bulk_g2s(dst0 + NODE_BYTES, leaf_values,              LEAF_BYTES, bar0);
        mbar_expect_tx(bar1, BUF_BYTES);
        bulk_g2s(dst1,              gN + NODE_CHUNK,          NODE_BYTES, bar1);
        bulk_g2s(dst1 + NODE_BYTES, leaf_values + LEAF_CHUNK, LEAF_BYTES, bar1);
    }

    // Stage x-code tile (coalesced per feature row)
    for (int ii = tid; ii < NFEAT * SPC; ii += TPB) {
        int ff = ii / SPC;
        int rr = ii - ff * SPC;
        int gs = min(base + rr, BATCH - 1);
        xsw[ff * SPC + rr] = g_xcode[(size_t)ff * BATCH + gs];
    }
    __syncthreads();

    float acc[NCLS];
    #pragma unroll
    for (int k = 0; k < NCLS; k++) acc[k] = 0.0f;

    const uint32_t* xcol = xsw + r;

    uint32_t barCur = bar0, barNxt = bar1;
    uint32_t dstCur = dst0, dstNxt = dst1;
    const char* pCur = smem_raw + BUF_OFF(0);
    const char* pNxt = smem_raw + BUF_OFF(1);
    int phCur = 0, phNxt = 0;

    for (int c = 0; c < NCHUNK; c++) {
        mbar_wait(barCur, phCur);
        phCur ^= 1;

        const uint32_t* nodeB = reinterpret_cast<const uint32_t*>(pCur);
        const float*    leafB = reinterpret_cast<const float*>(pCur + NODE_BYTES);

        // This thread owns stage q of the 4-stage chunk: 10 class-trees.
        #pragma unroll
        for (int k = 0; k < NCLS; k++) {
            const int tj = q * NCLS + k;
            const uint32_t* nt = nodeB + tj * NINT;
            uint32_t idx = 0;
            #pragma unroll
            for (int l = 0; l < 6; l++) {
                uint32_t nw = nt[idx];        // 1 wf
                uint32_t cd = xcol[nw >> 12]; // 1 wf (distinct banks per lane)
                idx = 2 * idx + 1 + (cd >= nw);  // prefix-equal compare
            }
            acc[k] += leafB[tj * NLEAF + ((int)idx - NINT)];
        }

        __syncthreads();
        if (c + 2 < NCHUNK && tid == 0) {
            const int nc = c + 2;
            mbar_expect_tx(barCur, BUF_BYTES);
            bulk_g2s(dstCur,              gN + (size_t)nc * NODE_CHUNK, NODE_BYTES, barCur);
            bulk_g2s(dstCur + NODE_BYTES, leaf_values + (size_t)nc * LEAF_CHUNK,
                     LEAF_BYTES, barCur);
        }

        uint32_t tb = barCur; barCur = barNxt; barNxt = tb;
        uint32_t td = dstCur; dstCur = dstNxt; dstNxt = td;
        const char* tp = pCur; pCur = pNxt; pNxt = tp;
        int tph = phCur; phCur = phNxt; phNxt = tph;
    }

    // Cross-quarter reduction (reuse x tile region; all reads done by last sync)
    float* red = reinterpret_cast<float*>(smem_raw);
    if (q > 0) {
        #pragma unroll
        for (int k = 0; k < NCLS; k++)
            red[((q - 1) * SPC + r) * NCLS + k] = acc[k];
    }
    __syncthreads();

    if (q == 0 && base + r < BATCH) {
        const int sample = base + r;
        #pragma unroll
        for (int k = 0; k < NCLS; k++) {
            float v = acc[k]
                    + red[(0 * SPC + r) * NCLS + k]
                    + red[(1 * SPC + r) * NCLS + k]
                    + red[(2 * SPC + r) * NCLS + k];
            out[(size_t)sample * NCLS + k] = __ldg(init_out + k) + LR * v;
        }
    }
}

extern "C" void kernel_launch(void* const* d_in, const int* in_sizes, int n_in,
                              void* d_out, int out_size)
{
    (void)in_sizes; (void)n_in; (void)out_size;

    const float* x           = (const float*)d_in[0];
    const int*   features    = (const int*)  d_in[1];
    const float* thresholds  = (const float*)d_in[2];
    const float* leaf_values = (const float*)d_in[3];
    const float* init_out    = (const float*)d_in[4];
    float*       out         = (float*)d_out;

    static bool attr_set = false;
    if (!attr_set) {
        cudaFuncSetAttribute(gbt_forest_kernel,
                             cudaFuncAttributeMaxDynamicSharedMemorySize, SMEM_TOTAL);
        cudaFuncSetAttribute(prep_sort_kernel,
                             cudaFuncAttributeMaxDynamicSharedMemorySize, SORT_SMEM);
        cudaFuncSetAttribute(prep_xcode_kernel,
                             cudaFuncAttributeMaxDynamicSharedMemorySize, XCODE_SMEM);
        attr_set = true;
    }

    prep_zero_kernel<<<1, NFEAT>>>();
    prep_scatter_kernel<<<SCTAS, STPB>>>(features, thresholds);
    prep_sort_kernel<<<NFEAT, 1024, SORT_SMEM>>>();
    prep_xcode_kernel<<<NFEAT * XCODE_SPLIT, 1024, XCODE_SMEM>>>(x);
    gbt_forest_kernel<<<GRID, TPB, SMEM_TOTAL>>>(leaf_values, init_out, out);
}

// round 13
// speedup vs baseline: 1.3854x; 1.0351x over previous
#include <cuda_runtime.h>
#include <cstdint>

// Problem constants
#define BATCH      32768
#define NFEAT      128
#define NTREES     4000
#define NINT       63
#define NLEAF      64
#define NCLS       10
#define LR         0.1f

// Main-kernel tiling: TWO CTAs per SM. 112 samples/CTA, 448 threads =
// 4 threads per sample (each owns 1 stage of every 4-stage chunk) -> 14 warps
// per CTA, 28 per SM (7/SMSP).
#define SPC        112
#define TPB        448
#define NWARPS     (TPB / 32)                  // 14
#define GRID       ((BATCH + SPC - 1) / SPC)   // 293

#define CHUNK_STAGES 4
#define CHUNK_TREES  (CHUNK_STAGES * NCLS)     // 40 trees per buffer
#define NCHUNK       (NTREES / CHUNK_TREES)    // 100

// Node word: ((f*SPC) << 12) | j ; x-code word: ((f*SPC) << 12) | c
// equal prefixes => (cd >= nw) <=> (c >= j)
#define NODE_CHUNK   (CHUNK_TREES * NINT)      // 2520 u32
#define NODE_BYTES   (NODE_CHUNK * 4)          // 10080
#define LEAF_CHUNK   (CHUNK_TREES * NLEAF)     // 2560 f32
#define LEAF_BYTES   (LEAF_CHUNK * 4)          // 10240
#define BUF_BYTES    (NODE_BYTES + LEAF_BYTES) // 20320

#define XS_BYTES    (NFEAT * SPC * 4)          // 57344
#define BUF_OFF(b)  (XS_BYTES + (b) * BUF_BYTES)
#define MBAR_OFF    (XS_BYTES + 2 * BUF_BYTES) // 97984; full[2]+empty[2] = 32B
#define SMEM_TOTAL  (MBAR_OFF + 32)            // 98016 (x2 <= carveout)

#define SORTN 4096
#define FSEG  3072
#define REP_NODES 255
#define SORT_SMEM  (SORTN * 4)
#define XCODE_SMEM (SORTN * 4 + REP_NODES * 32 * 4)     // 48976
#define XCODE_SPLIT 4
#define XCODE_SAMP  (BATCH / XCODE_SPLIT)                // 8192
#define XCODE_ILP   8

// Scatter kernel shape
#define SCTAS   64
#define STPB    512
#define PER_TH  8
#define NELEMS  (NTREES * NINT)

// Device-global scratch (rebuilt deterministically every launch)
__device__ __align__(16) uint32_t g_nodesQ[NTREES * NINT];
__device__ __align__(16) uint32_t g_xcode[(size_t)NFEAT * BATCH];
__device__ __align__(16) uint32_t g_skey[(size_t)NFEAT * SORTN];
__device__ __align__(16) float    g_xT[(size_t)NFEAT * BATCH];
__device__ int      g_fcount[NFEAT];
__device__ uint64_t g_tpair[(size_t)NFEAT * FSEG];

extern __shared__ char smem_raw[];

__device__ __forceinline__ uint32_t fkey(float v) {
    int b = __float_as_int(v);
    return (uint32_t)(b ^ ((b >> 31) | 0x80000000));
}

__device__ __forceinline__ uint32_t s2u(const void* p) {
    uint32_t a;
    asm("{ .reg .u64 t; cvta.to.shared.u64 t, %1; cvt.u32.u64 %0, t; }"
        : "=r"(a) : "l"(p));
    return a;
}

__device__ __forceinline__ void mbar_init(uint32_t bar, uint32_t cnt) {
    asm volatile("mbarrier.init.shared.b64 [%0], %1;" :: "r"(bar), "r"(cnt) : "memory");
}

__device__ __forceinline__ void mbar_arrive(uint32_t bar) {
    asm volatile("mbarrier.arrive.release.cta.shared::cta.b64 _, [%0];"
                 :: "r"(bar) : "memory");
}

__device__ __forceinline__ void mbar_expect_tx(uint32_t bar, uint32_t bytes) {
    asm volatile("mbarrier.arrive.expect_tx.shared.b64 _, [%0], %1;"
                 :: "r"(bar), "r"(bytes) : "memory");
}

__device__ __forceinline__ void mbar_wait(uint32_t bar, uint32_t parity) {
    uint32_t done;
    asm volatile(
        "{\n\t.reg .pred p;\n\t"
        "mbarrier.try_wait.parity.acquire.cta.shared::cta.b64 p, [%1], %2;\n\t"
        "selp.b32 %0, 1, 0, p;\n\t}"
        : "=r"(done) : "r"(bar), "r"(parity) : "memory");
    while (!done) {
        asm volatile(
            "{\n\t.reg .pred p;\n\t"
            "mbarrier.try_wait.parity.acquire.cta.shared::cta.b64 p, [%1], %2, 0x989680;\n\t"
            "selp.b32 %0, 1, 0, p;\n\t}"
            : "=r"(done) : "r"(bar), "r"(parity) : "memory");
    }
}

__device__ __forceinline__ void bulk_g2s(uint32_t dst, const void* src,
                                         uint32_t bytes, uint32_t bar) {
    asm volatile(
        "cp.async.bulk.shared::cluster.global.mbarrier::complete_tx::bytes "
        "[%0], [%1], %2, [%3];"
        :: "r"(dst), "l"(src), "r"(bytes), "r"(bar) : "memory");
}

// ============================ prep kernels ============================

__global__ void prep_zero_kernel() {
    if (threadIdx.x < NFEAT) g_fcount[threadIdx.x] = 0;
}

__global__ void __launch_bounds__(STPB, 1)
prep_scatter_kernel(const int* __restrict__ features,
                    const float* __restrict__ thresholds)
{
    __shared__ int h[NFEAT];
    __shared__ int hbase[NFEAT];
    const int tid = threadIdx.x;

    for (int i = tid; i < NFEAT; i += STPB) h[i] = 0;
    __syncthreads();

    int      fv[PER_TH];
    uint32_t kv[PER_TH];
    const int base = blockIdx.x * (STPB * PER_TH);

    #pragma unroll
    for (int e = 0; e < PER_TH; e++) {
        int i = base + e * STPB + tid;
        fv[e] = -1;
        if (i < NELEMS) {
            fv[e] = features[i];
            kv[e] = fkey(thresholds[i] + 0.0f);
            atomicAdd(&h[fv[e]], 1);
        }
    }
    __syncthreads();

    for (int i = tid; i < NFEAT; i += STPB) {
        hbase[i] = atomicAdd(&g_fcount[i], h[i]);
        h[i] = 0;
    }
    __syncthreads();

    #pragma unroll
    for (int e = 0; e < PER_TH; e++) {
        if (fv[e] >= 0) {
            int i   = base + e * STPB + tid;
            int off = hbase[fv[e]] + atomicAdd(&h[fv[e]], 1);
            g_tpair[(size_t)fv[e] * FSEG + off] =
                ((uint64_t)kv[e] << 32) | (uint32_t)i;
        }
    }
}

// Transpose x [BATCH, NFEAT] -> g_xT [NFEAT, BATCH] (coalesced both ways).
__global__ void __launch_bounds__(256, 2)
prep_transpose_kernel(const float* __restrict__ x)
{
    __shared__ float t[32][33];
    const int tx = threadIdx.x;
    const int ty = threadIdx.y;
    const int sBase = blockIdx.x * 32;
    const int fBase = blockIdx.y * 32;

    #pragma unroll
    for (int rr = ty; rr < 32; rr += 8)
        t[rr][tx] = x[(size_t)(sBase + rr) * NFEAT + fBase + tx];
    __syncthreads();
    #pragma unroll
    for (int rr = ty; rr < 32; rr += 8)
        g_xT[(size_t)(fBase + rr) * BATCH + sBase + tx] = t[tx][rr];
}

// Per-feature: bitonic-sort keys, emit node codes, publish sorted keys.
__global__ void __launch_bounds__(1024, 1)
prep_sort_kernel()
{
    extern __shared__ char sm4[];
    uint32_t* skey = reinterpret_cast<uint32_t*>(sm4);

    const int f   = blockIdx.x;
    const int tid = threadIdx.x;
    const int m   = g_fcount[f];
    const uint64_t* seg = g_tpair + (size_t)f * FSEG;
    const uint32_t prefix = (uint32_t)(f * SPC) << 12;

    for (int p = tid; p < SORTN; p += 1024)
        skey[p] = (p < m) ? (uint32_t)(seg[p] >> 32) : 0xFFFFFFFFu;
    __syncthreads();

    for (int k = 2; k <= SORTN; k <<= 1) {
        for (int jj = k >> 1; jj > 0; jj >>= 1) {
            for (int i = tid; i < SORTN; i += 1024) {
                int p = i ^ jj;
                if (p > i) {
                    uint32_t a = skey[i], b = skey[p];
                    bool up = ((i & k) == 0);
                    if ((a > b) == up) { skey[i] = b; skey[p] = a; }
                }
            }
            __syncthreads();
        }
    }

    for (int p = tid; p < m; p += 1024) {
        uint64_t pr  = seg[p];
        uint32_t key = (uint32_t)(pr >> 32);
        uint32_t id  = (uint32_t)(pr & 0xFFFFFFFFull);
        int pos = 0;
        #pragma unroll
        for (int w = SORTN >> 1; w >= 1; w >>= 1)
            if (skey[pos + w - 1] <= key) pos += w;
        g_nodesQ[id] = prefix | (uint32_t)pos;
    }

    for (int p = tid; p < SORTN; p += 1024)
        g_skey[(size_t)f * SORTN + p] = skey[p];
}

// 4 CTAs per feature; 8 interleaved search chains per thread (MLP), reads
// from transposed x (coalesced).
__global__ void __launch_bounds__(1024, 1)
prep_xcode_kernel()
{
    extern __shared__ char sm4[];
    uint32_t* skey = reinterpret_cast<uint32_t*>(sm4);
    uint32_t* rep  = reinterpret_cast<uint32_t*>(sm4 + SORTN * 4);

    const int f    = blockIdx.x >> 2;
    const int part = blockIdx.x & 3;
    const int tid  = threadIdx.x;
    const int lane = tid & 31;
    const uint32_t prefix = (uint32_t)(f * SPC) << 12;

    for (int p = tid; p < SORTN; p += 1024)
        skey[p] = g_skey[(size_t)f * SORTN + p];
    __syncthreads();

    for (int i = tid; i < REP_NODES * 32; i += 1024) {
        int nb = i >> 5;
        int L  = 31 - __clz(nb + 1);
        int q  = (nb + 1) - (1 << L);
        int w  = 2048 >> L;
        rep[i] = skey[(2 * q + 1) * w - 1];
    }
    __syncthreads();

    const int sBase = part * XCODE_SAMP;          // 8192 samples, 8 per thread
    uint32_t key[XCODE_ILP];
    int      qn [XCODE_ILP];

    #pragma unroll
    for (int i = 0; i < XCODE_ILP; i++) {
        int s  = sBase + i * 1024 + tid;
        key[i] = fkey(g_xT[(size_t)f * BATCH + s] + 0.0f);   // coalesced
        qn[i]  = 0;
    }
    #pragma unroll
    for (int L = 0; L < 8; L++) {
        #pragma unroll
        for (int i = 0; i < XCODE_ILP; i++) {
            uint32_t tk = rep[(((1 << L) - 1 + qn[i]) << 5) + lane];
            qn[i] = 2 * qn[i] + (tk < key[i]);
        }
    }
    #pragma unroll
    for (int i = 0; i < XCODE_ILP; i++) {
        int pos = qn[i] << 4;
        if (skey[pos + 7] < key[i]) pos += 8;
        if (skey[pos + 3] < key[i]) pos += 4;
        if (skey[pos + 1] < key[i]) pos += 2;
        if (skey[pos]     < key[i]) pos += 1;
        int s = sBase + i * 1024 + tid;
        g_xcode[(size_t)f * BATCH + s] = prefix | (uint32_t)pos;
    }
}

// ============================ main kernel ============================

__global__ void __launch_bounds__(TPB, 2)
gbt_forest_kernel(const float* __restrict__ leaf_values,
                  const float* __restrict__ init_out,
                  float*       __restrict__ out)
{
    uint32_t* xsw = reinterpret_cast<uint32_t*>(smem_raw);
    uint64_t* mbar = reinterpret_cast<uint64_t*>(smem_raw + MBAR_OFF);

    const int tid  = threadIdx.x;
    const int lane = tid & 31;
    const int q    = tid / SPC;           // stage quarter 0..3
    const int r    = tid - q * SPC;       // sample slot 0..111
    const int base = blockIdx.x * SPC;

    const uint32_t full0  = s2u(&mbar[0]);
    const uint32_t full1  = s2u(&mbar[1]);
    const uint32_t empty0 = s2u(&mbar[2]);
    const uint32_t empty1 = s2u(&mbar[3]);
    const uint32_t dst0   = s2u(smem_raw + BUF_OFF(0));
    const uint32_t dst1   = s2u(smem_raw + BUF_OFF(1));

    const uint32_t* gN = g_nodesQ;

    if (tid == 0) {
        mbar_init(full0, 1);
        mbar_init(full1, 1);
        mbar_init(empty0, NWARPS);
        mbar_init(empty1, NWARPS);
        asm volatile("fence.proxy.async.shared::cta;" ::: "memory");
        mbar_expect_tx(full0, BUF_BYTES);
        bulk_g2s(dst0,              gN,                       NODE_BYTES, full0);
        bulk_g2s(dst0 + NODE_BYTES, leaf_values,              LEAF_BYTES, full0);
        mbar_expect_tx(full1, BUF_BYTES);
        bulk_g2s(dst1,              gN + NODE_CHUNK,          NODE_BYTES, full1);
        bulk_g2s(dst1 + NODE_BYTES, leaf_values + LEAF_CHUNK, LEAF_BYTES, full1);
    }

    // Stage x-code tile
    for (int ii = tid; ii < NFEAT * SPC; ii += TPB) {
        int ff = ii / SPC;
        int rr = ii - ff * SPC;
        int gs = min(base + rr, BATCH - 1);
        xsw[ff * SPC + rr] = g_xcode[(size_t)ff * BATCH + gs];
    }
    __syncthreads();   // barriers initialized + tile staged, visible to all

    float acc[NCLS];
    #pragma unroll
    for (int k = 0; k < NCLS; k++) acc[k] = 0.0f;

    const uint32_t* xcol = xsw + r;

    for (int c = 0; c < NCHUNK; c++) {
        const int b  = c & 1;
        const int ph = (c >> 1) & 1;
        const uint32_t fullB  = b ? full1 : full0;
        const uint32_t emptyB = b ? empty1 : empty0;
        const char* pCur = smem_raw + BUF_OFF(b);

        mbar_wait(fullB, ph);

        const uint32_t* nodeB = reinterpret_cast<const uint32_t*>(pCur);
        const float*    leafB = reinterpret_cast<const float*>(pCur + NODE_BYTES);

        #pragma unroll
        for (int k = 0; k < NCLS; k++) {
            const int tj = q * NCLS + k;
            const uint32_t* nt = nodeB + tj * NINT;
            uint32_t idx = 0;
            #pragma unroll
            for (int l = 0; l < 6; l++) {
                uint32_t nw = nt[idx];
                uint32_t cd = xcol[nw >> 12];
                idx = 2 * idx + 1 + (cd >= nw);
            }
            acc[k] += leafB[tj * NLEAF + ((int)idx - NINT)];
        }

        // Warp-level "done with buffer" arrive; warps skew freely (bound = 2 bufs)
        __syncwarp();
        if (lane == 0) mbar_arrive(emptyB);

        // Producer (tid 0): wait all 14 warps done, then refill this buffer
        if (tid == 0 && c + 2 < NCHUNK) {
            mbar_wait(emptyB, ph);
            asm volatile("fence.proxy.async.shared::cta;" ::: "memory");
            const int nc = c + 2;
            const uint32_t dstB = b ? dst1 : dst0;
            mbar_expect_tx(fullB, BUF_BYTES);
            bulk_g2s(dstB,              gN + (size_t)nc * NODE_CHUNK, NODE_BYTES, fullB);
            bulk_g2s(dstB + NODE_BYTES, leaf_values + (size_t)nc * LEAF_CHUNK,
                     LEAF_BYTES, fullB);
        }
    }

    __syncthreads();   // all warps done reading xsw before red[] overwrites it

    float* red = reinterpret_cast<float*>(smem_raw);
    if (q > 0) {
        #pragma unroll
        for (int k = 0; k < NCLS; k++)
            red[((q - 1) * SPC + r) * NCLS + k] = acc[k];
    }
    __syncthreads();

    if (q == 0 && base + r < BATCH) {
        const int sample = base + r;
        #pragma unroll
        for (int k = 0; k < NCLS; k++) {
            float v = acc[k]
                    + red[(0 * SPC + r) * NCLS + k]
                    + red[(1 * SPC + r) * NCLS + k]
                    + red[(2 * SPC + r) * NCLS + k];
            out[(size_t)sample * NCLS + k] = __ldg(init_out + k) + LR * v;
        }
    }
}

extern "C" void kernel_launch(void* const* d_in, const int* in_sizes, int n_in,
                              void* d_out, int out_size)
{
    (void)in_sizes; (void)n_in; (void)out_size;

    const float* x           = (const float*)d_in[0];
    const int*   features    = (const int*)  d_in[1];
    const float* thresholds  = (const float*)d_in[2];
    const float* leaf_values = (const float*)d_in[3];
    const float* init_out    = (const float*)d_in[4];
    float*       out         = (float*)d_out;

    static bool attr_set = false;
    if (!attr_set) {
        cudaFuncSetAttribute(gbt_forest_kernel,
                             cudaFuncAttributeMaxDynamicSharedMemorySize, SMEM_TOTAL);
        cudaFuncSetAttribute(prep_sort_kernel,
                             cudaFuncAttributeMaxDynamicSharedMemorySize, SORT_SMEM);
        cudaFuncSetAttribute(prep_xcode_kernel,
                             cudaFuncAttributeMaxDynamicSharedMemorySize, XCODE_SMEM);
        attr_set = true;
    }

    prep_zero_kernel<<<1, NFEAT>>>();
    prep_scatter_kernel<<<SCTAS, STPB>>>(features, thresholds);
    {
        dim3 tb(32, 8);
        dim3 tg(BATCH / 32, NFEAT / 32);
        prep_transpose_kernel<<<tg, tb>>>(x);
    }
    prep_sort_kernel<<<NFEAT, 1024, SORT_SMEM>>>();
    prep_xcode_kernel<<<NFEAT * XCODE_SPLIT, 1024, XCODE_SMEM>>>();
    gbt_forest_kernel<<<GRID, TPB, SMEM_TOTAL>>>(leaf_values, init_out, out);
}

// round 14
// speedup vs baseline: 1.3896x; 1.0030x over previous
#include <cuda_runtime.h>
#include <cstdint>

// Problem constants
#define BATCH      32768
#define NFEAT      128
#define NTREES     4000
#define NINT       63
#define NLEAF      64
#define NCLS       10
#define LR         0.1f

// Main-kernel tiling: TWO CTAs per SM. 112 samples/CTA, 448 threads =
// 4 threads per sample (each owns 1 stage of every 4-stage chunk) -> 14 warps
// per CTA, 28 per SM (7/SMSP).
#define SPC        112
#define TPB        448
#define NWARPS     (TPB / 32)                  // 14
#define GRID       ((BATCH + SPC - 1) / SPC)   // 293

#define CHUNK_STAGES 4
#define CHUNK_TREES  (CHUNK_STAGES * NCLS)     // 40 trees per buffer
#define NCHUNK       (NTREES / CHUNK_TREES)    // 100

// Node word: ((f*SPC) << 12) | j ; x-code word: ((f*SPC) << 12) | c
// equal prefixes => (cd >= nw) <=> (c >= j)
#define NODE_CHUNK   (CHUNK_TREES * NINT)      // 2520 u32
#define NODE_BYTES   (NODE_CHUNK * 4)          // 10080
#define LEAF_CHUNK   (CHUNK_TREES * NLEAF)     // 2560 f32
#define LEAF_BYTES   (LEAF_CHUNK * 4)          // 10240
#define BUF_BYTES    (NODE_BYTES + LEAF_BYTES) // 20320

#define XS_BYTES    (NFEAT * SPC * 4)          // 57344
#define BUF_OFF(b)  (XS_BYTES + (b) * BUF_BYTES)
#define MBAR_OFF    (XS_BYTES + 2 * BUF_BYTES) // 97984
#define SMEM_TOTAL  (MBAR_OFF + 32)            // 98016 (x2 <= carveout)

#define SORTN 4096
#define FSEG  3072
#define REP_NODES 255
#define SORT_SMEM  (SORTN * 4)
#define XCODE_SMEM (SORTN * 4 + REP_NODES * 32 * 4)     // 48976
#define XCODE_SPLIT 4
#define XCODE_SAMP  (BATCH / XCODE_SPLIT)                // 8192
#define XCODE_ILP   8

// Scatter kernel shape
#define SCTAS   64
#define STPB    512
#define PER_TH  8
#define NELEMS  (NTREES * NINT)

// Device-global scratch (rebuilt deterministically every launch)
__device__ __align__(16) uint32_t g_nodesQ[NTREES * NINT];
__device__ __align__(16) uint32_t g_xcode[(size_t)NFEAT * BATCH];
__device__ __align__(16) uint32_t g_skey[(size_t)NFEAT * SORTN];
__device__ __align__(16) float    g_xT[(size_t)NFEAT * BATCH];
__device__ int      g_fcount[NFEAT];
__device__ uint64_t g_tpair[(size_t)NFEAT * FSEG];

extern __shared__ char smem_raw[];

__device__ __forceinline__ uint32_t fkey(float v) {
    int b = __float_as_int(v);
    return (uint32_t)(b ^ ((b >> 31) | 0x80000000));
}

__device__ __forceinline__ uint32_t s2u(const void* p) {
    uint32_t a;
    asm("{ .reg .u64 t; cvta.to.shared.u64 t, %1; cvt.u32.u64 %0, t; }"
        : "=r"(a) : "l"(p));
    return a;
}

__device__ __forceinline__ void mbar_init(uint32_t bar, uint32_t cnt) {
    asm volatile("mbarrier.init.shared.b64 [%0], %1;" :: "r"(bar), "r"(cnt) : "memory");
}

__device__ __forceinline__ void mbar_arrive(uint32_t bar) {
    asm volatile("mbarrier.arrive.release.cta.shared::cta.b64 _, [%0];"
                 :: "r"(bar) : "memory");
}

__device__ __forceinline__ void mbar_expect_tx(uint32_t bar, uint32_t bytes) {
    asm volatile("mbarrier.arrive.expect_tx.shared.b64 _, [%0], %1;"
                 :: "r"(bar), "r"(bytes) : "memory");
}

__device__ __forceinline__ void mbar_wait(uint32_t bar, uint32_t parity) {
    uint32_t done;
    asm volatile(
        "{\n\t.reg .pred p;\n\t"
        "mbarrier.try_wait.parity.acquire.cta.shared::cta.b64 p, [%1], %2;\n\t"
        "selp.b32 %0, 1, 0, p;\n\t}"
        : "=r"(done) : "r"(bar), "r"(parity) : "memory");
    while (!done) {
        asm volatile(
            "{\n\t.reg .pred p;\n\t"
            "mbarrier.try_wait.parity.acquire.cta.shared::cta.b64 p, [%1], %2, 0x989680;\n\t"
            "selp.b32 %0, 1, 0, p;\n\t}"
            : "=r"(done) : "r"(bar), "r"(parity) : "memory");
    }
}

__device__ __forceinline__ void bulk_g2s(uint32_t dst, const void* src,
                                         uint32_t bytes, uint32_t bar) {
    asm volatile(
        "cp.async.bulk.shared::cluster.global.mbarrier::complete_tx::bytes "
        "[%0], [%1], %2, [%3];"
        :: "r"(dst), "l"(src), "r"(bytes), "r"(bar) : "memory");
}

// ============================ prep kernels ============================

// Transpose x [BATCH, NFEAT] -> g_xT [NFEAT, BATCH]; block (0,0) also zeros
// the feature counters (runs before scatter on the same stream).
__global__ void __launch_bounds__(256, 2)
prep_transpose_kernel(const float* __restrict__ x)
{
    __shared__ float t[32][33];
    const int tx = threadIdx.x;
    const int ty = threadIdx.y;
    const int flat = ty * 32 + tx;
    const int sBase = blockIdx.x * 32;
    const int fBase = blockIdx.y * 32;

    if (blockIdx.x == 0 && blockIdx.y == 0 && flat < NFEAT)
        g_fcount[flat] = 0;

    #pragma unroll
    for (int rr = ty; rr < 32; rr += 8)
        t[rr][tx] = x[(size_t)(sBase + rr) * NFEAT + fBase + tx];
    __syncthreads();
    #pragma unroll
    for (int rr = ty; rr < 32; rr += 8)
        g_xT[(size_t)(fBase + rr) * BATCH + sBase + tx] = t[tx][rr];
}

__global__ void __launch_bounds__(STPB, 1)
prep_scatter_kernel(const int* __restrict__ features,
                    const float* __restrict__ thresholds)
{
    __shared__ int h[NFEAT];
    __shared__ int hbase[NFEAT];
    const int tid = threadIdx.x;

    for (int i = tid; i < NFEAT; i += STPB) h[i] = 0;
    __syncthreads();

    int      fv[PER_TH];
    uint32_t kv[PER_TH];
    const int base = blockIdx.x * (STPB * PER_TH);

    #pragma unroll
    for (int e = 0; e < PER_TH; e++) {
        int i = base + e * STPB + tid;
        fv[e] = -1;
        if (i < NELEMS) {
            fv[e] = features[i];
            kv[e] = fkey(thresholds[i] + 0.0f);
            atomicAdd(&h[fv[e]], 1);
        }
    }
    __syncthreads();

    for (int i = tid; i < NFEAT; i += STPB) {
        hbase[i] = atomicAdd(&g_fcount[i], h[i]);
        h[i] = 0;
    }
    __syncthreads();

    #pragma unroll
    for (int e = 0; e < PER_TH; e++) {
        if (fv[e] >= 0) {
            int i   = base + e * STPB + tid;
            int off = hbase[fv[e]] + atomicAdd(&h[fv[e]], 1);
            g_tpair[(size_t)fv[e] * FSEG + off] =
                ((uint64_t)kv[e] << 32) | (uint32_t)i;
        }
    }
}

// Per-feature bitonic sort with register/warp fusion:
//   each thread owns 4 consecutive elements; phases jj<=2 in registers,
//   jj in {4..64} via shfl.bfly, only jj>=128 via smem (+barrier).
//   78 barrier phases -> ~22.
__global__ void __launch_bounds__(1024, 1)
prep_sort_kernel()
{
    extern __shared__ char sm4[];
    uint32_t* skey = reinterpret_cast<uint32_t*>(sm4);

    const int f    = blockIdx.x;
    const int tid  = threadIdx.x;
    const int lane = tid & 31;
    const int m    = g_fcount[f];
    const uint64_t* seg = g_tpair + (size_t)f * FSEG;
    const uint32_t prefix = (uint32_t)(f * SPC) << 12;

    for (int p = tid; p < SORTN; p += 1024)
        skey[p] = (p < m) ? (uint32_t)(seg[p] >> 32) : 0xFFFFFFFFu;
    __syncthreads();

    uint32_t v[4];

    // One bitonic phase (jj <= 64) on register-resident elements.
    auto warp_phase = [&](int jj, int k) {
        if (jj >= 4) {
            const int lm = jj >> 2;
            #pragma unroll
            for (int e = 0; e < 4; e++) {
                uint32_t o = __shfl_xor_sync(0xffffffffu, v[e], lm);
                int  i     = (tid << 2) + e;
                bool up    = ((i & k) == 0);
                bool lower = ((lane & lm) == 0);
                uint32_t mn = min(v[e], o), mx = max(v[e], o);
                v[e] = (lower == up) ? mn : mx;
            }
        } else {
            #pragma unroll
            for (int e = 0; e < 4; e++) {
                int pe = e ^ jj;
                if (pe > e) {
                    int  i  = (tid << 2) + e;
                    bool up = ((i & k) == 0);
                    uint32_t a = v[e], b = v[pe];
                    if ((a > b) == up) { v[e] = b; v[pe] = a; }
                }
            }
        }
    };

    // Session 1: k = 2..128 entirely register/warp-local (1 barrier).
    #pragma unroll
    for (int e = 0; e < 4; e++) v[e] = skey[(tid << 2) + e];
    for (int k = 2; k <= 128; k <<= 1)
        for (int jj = k >> 1; jj >= 1; jj >>= 1)
            warp_phase(jj, k);
    #pragma unroll
    for (int e = 0; e < 4; e++) skey[(tid << 2) + e] = v[e];
    __syncthreads();

    // k = 256..4096: smem phases for jj >= 128, then fused warp tail.
    for (int k = 256; k <= SORTN; k <<= 1) {
        for (int jj = k >> 1; jj >= 128; jj >>= 1) {
            for (int i = tid; i < SORTN; i += 1024) {
                int p = i ^ jj;
                if (p > i) {
                    uint32_t a = skey[i], b = skey[p];
                    bool up = ((i & k) == 0);
                    if ((a > b) == up) { skey[i] = b; skey[p] = a; }
                }
            }
            __syncthreads();
        }
        #pragma unroll
        for (int e = 0; e < 4; e++) v[e] = skey[(tid << 2) + e];
        for (int jj = 64; jj >= 1; jj >>= 1)
            warp_phase(jj, k);
        #pragma unroll
        for (int e = 0; e < 4; e++) skey[(tid << 2) + e] = v[e];
        __syncthreads();
    }

    // Node codes: j = upper_bound (<=)
    for (int p = tid; p < m; p += 1024) {
        uint64_t pr  = seg[p];
        uint32_t key = (uint32_t)(pr >> 32);
        uint32_t id  = (uint32_t)(pr & 0xFFFFFFFFull);
        int pos = 0;
        #pragma unroll
        for (int w = SORTN >> 1; w >= 1; w >>= 1)
            if (skey[pos + w - 1] <= key) pos += w;
        g_nodesQ[id] = prefix | (uint32_t)pos;
    }

    // Publish sorted keys for the xcode kernel
    for (int p = tid; p < SORTN; p += 1024)
        g_skey[(size_t)f * SORTN + p] = skey[p];
}

// 4 CTAs per feature; 8 interleaved search chains per thread, coalesced x reads.
__global__ void __launch_bounds__(1024, 1)
prep_xcode_kernel()
{
    extern __shared__ char sm4[];
    uint32_t* skey = reinterpret_cast<uint32_t*>(sm4);
    uint32_t* rep  = reinterpret_cast<uint32_t*>(sm4 + SORTN * 4);

    const int f    = blockIdx.x >> 2;
    const int part = blockIdx.x & 3;
    const int tid  = threadIdx.x;
    const int lane = tid & 31;
    const uint32_t prefix = (uint32_t)(f * SPC) << 12;

    for (int p = tid; p < SORTN; p += 1024)
        skey[p] = g_skey[(size_t)f * SORTN + p];
    __syncthreads();

    for (int i = tid; i < REP_NODES * 32; i += 1024) {
        int nb = i >> 5;
        int L  = 31 - __clz(nb + 1);
        int q  = (nb + 1) - (1 << L);
        int w  = 2048 >> L;
        rep[i] = skey[(2 * q + 1) * w - 1];
    }
    __syncthreads();

    const int sBase = part * XCODE_SAMP;
    uint32_t key[XCODE_ILP];
    int      qn [XCODE_ILP];

    #pragma unroll
    for (int i = 0; i < XCODE_ILP; i++) {
        int s  = sBase + i * 1024 + tid;
        key[i] = fkey(g_xT[(size_t)f * BATCH + s] + 0.0f);
        qn[i]  = 0;
    }
    #pragma unroll
    for (int L = 0; L < 8; L++) {
        #pragma unroll
        for (int i = 0; i < XCODE_ILP; i++) {
            uint32_t tk = rep[(((1 << L) - 1 + qn[i]) << 5) + lane];
            qn[i] = 2 * qn[i] + (tk < key[i]);
        }
    }
    #pragma unroll
    for (int i = 0; i < XCODE_ILP; i++) {
        int pos = qn[i] << 4;
        if (skey[pos + 7] < key[i]) pos += 8;
        if (skey[pos + 3] < key[i]) pos += 4;
        if (skey[pos + 1] < key[i]) pos += 2;
        if (skey[pos]     < key[i]) pos += 1;
        int s = sBase + i * 1024 + tid;
        g_xcode[(size_t)f * BATCH + s] = prefix | (uint32_t)pos;
    }
}

// ============================ main kernel ============================

__global__ void __launch_bounds__(TPB, 2)
gbt_forest_kernel(const float* __restrict__ leaf_values,
                  const float* __restrict__ init_out,
                  float*       __restrict__ out)
{
    uint32_t* xsw = reinterpret_cast<uint32_t*>(smem_raw);
    uint64_t* mbar = reinterpret_cast<uint64_t*>(smem_raw + MBAR_OFF);

    const int tid  = threadIdx.x;
    const int lane = tid & 31;
    const int q    = tid / SPC;
    const int r    = tid - q * SPC;
    const int base = blockIdx.x * SPC;

    const uint32_t full0  = s2u(&mbar[0]);
    const uint32_t full1  = s2u(&mbar[1]);
    const uint32_t empty0 = s2u(&mbar[2]);
    const uint32_t empty1 = s2u(&mbar[3]);
    const uint32_t dst0   = s2u(smem_raw + BUF_OFF(0));
    const uint32_t dst1   = s2u(smem_raw + BUF_OFF(1));

    const uint32_t* gN = g_nodesQ;

    if (tid == 0) {
        mbar_init(full0, 1);
        mbar_init(full1, 1);
        mbar_init(empty0, NWARPS);
        mbar_init(empty1, NWARPS);
        asm volatile("fence.proxy.async.shared::cta;" ::: "memory");
        mbar_expect_tx(full0, BUF_BYTES);
        bulk_g2s(dst0,              gN,                       NODE_BYTES, full0);
        bulk_g2s(dst0 + NODE_BYTES, leaf_values,              LEAF_BYTES, full0);
        mbar_expect_tx(full1, BUF_BYTES);
        bulk_g2s(dst1,              gN + NODE_CHUNK,          NODE_BYTES, full1);
        bulk_g2s(dst1 + NODE_BYTES, leaf_values + LEAF_CHUNK, LEAF_BYTES, full1);
    }

    for (int ii = tid; ii < NFEAT * SPC; ii += TPB) {
        int ff = ii / SPC;
        int rr = ii - ff * SPC;
        int gs = min(base + rr, BATCH - 1);
        xsw[ff * SPC + rr] = g_xcode[(size_t)ff * BATCH + gs];
    }
    __syncthreads();

    float acc[NCLS];
    #pragma unroll
    for (int k = 0; k < NCLS; k++) acc[k] = 0.0f;

    const uint32_t* xcol = xsw + r;

    for (int c = 0; c < NCHUNK; c++) {
        const int b  = c & 1;
        const int ph = (c >> 1) & 1;
        const uint32_t fullB  = b ? full1 : full0;
        const uint32_t emptyB = b ? empty1 : empty0;
        const char* pCur = smem_raw + BUF_OFF(b);

        mbar_wait(fullB, ph);

        const uint32_t* nodeB = reinterpret_cast<const uint32_t*>(pCur);
        const float*    leafB = reinterpret_cast<const float*>(pCur + NODE_BYTES);

        #pragma unroll
        for (int k = 0; k < NCLS; k++) {
            const int tj = q * NCLS + k;
            const uint32_t* nt = nodeB + tj * NINT;
            uint32_t idx = 0;
            #pragma unroll
            for (int l = 0; l < 6; l++) {
                uint32_t nw = nt[idx];
                uint32_t cd = xcol[nw >> 12];
                idx = 2 * idx + 1 + (cd >= nw);
            }
            acc[k] += leafB[tj * NLEAF + ((int)idx - NINT)];
        }

        __syncwarp();
        if (lane == 0) mbar_arrive(emptyB);

        if (tid == 0 && c + 2 < NCHUNK) {
            mbar_wait(emptyB, ph);
            asm volatile("fence.proxy.async.shared::cta;" ::: "memory");
            const int nc = c + 2;
            const uint32_t dstB = b ? dst1 : dst0;
            mbar_expect_tx(fullB, BUF_BYTES);
            bulk_g2s(dstB,              gN + (size_t)nc * NODE_CHUNK, NODE_BYTES, fullB);
            bulk_g2s(dstB + NODE_BYTES, leaf_values + (size_t)nc * LEAF_CHUNK,
                     LEAF_BYTES, fullB);
        }
    }

    __syncthreads();

    float* red = reinterpret_cast<float*>(smem_raw);
    if (q > 0) {
        #pragma unroll
        for (int k = 0; k < NCLS; k++)
            red[((q - 1) * SPC + r) * NCLS + k] = acc[k];
    }
    __syncthreads();

    if (q == 0 && base + r < BATCH) {
        const int sample = base + r;
        #pragma unroll
        for (int k = 0; k < NCLS; k++) {
            float v = acc[k]
                    + red[(0 * SPC + r) * NCLS + k]
                    + red[(1 * SPC + r) * NCLS + k]
                    + red[(2 * SPC + r) * NCLS + k];
            out[(size_t)sample * NCLS + k] = __ldg(init_out + k) + LR * v;
        }
    }
}

extern "C" void kernel_launch(void* const* d_in, const int* in_sizes, int n_in,
                              void* d_out, int out_size)
{
    (void)in_sizes; (void)n_in; (void)out_size;

    const float* x           = (const float*)d_in[0];
    const int*   features    = (const int*)  d_in[1];
    const float* thresholds  = (const float*)d_in[2];
    const float* leaf_values = (const float*)d_in[3];
    const float* init_out    = (const float*)d_in[4];
    float*       out         = (float*)d_out;

    static bool attr_set = false;
    if (!attr_set) {
        cudaFuncSetAttribute(gbt_forest_kernel,
                             cudaFuncAttributeMaxDynamicSharedMemorySize, SMEM_TOTAL);
        cudaFuncSetAttribute(prep_sort_kernel,
                             cudaFuncAttributeMaxDynamicSharedMemorySize, SORT_SMEM);
        cudaFuncSetAttribute(prep_xcode_kernel,
                             cudaFuncAttributeMaxDynamicSharedMemorySize, XCODE_SMEM);
        attr_set = true;
    }

    {
        dim3 tb(32, 8);
        dim3 tg(BATCH / 32, NFEAT / 32);
        prep_transpose_kernel<<<tg, tb>>>(x);   // also zeros g_fcount
    }
    prep_scatter_kernel<<<SCTAS, STPB>>>(features, thresholds);
    prep_sort_kernel<<<NFEAT, 1024, SORT_SMEM>>>();
    prep_xcode_kernel<<<NFEAT * XCODE_SPLIT, 1024, XCODE_SMEM>>>();
    gbt_forest_kernel<<<GRID, TPB, SMEM_TOTAL>>>(leaf_values, init_out, out);
}

// round 15
// speedup vs baseline: 1.4852x; 1.0688x over previous
#include <cuda_runtime.h>
#include <cstdint>

// Problem constants
#define BATCH      32768
#define NFEAT      128
#define NTREES     4000
#define NINT       63
#define NLEAF      64
#define NCLS       10
#define LR         0.1f

// Main-kernel tiling: TWO CTAs per SM. 112 samples/CTA, 448 threads =
// 4 threads per sample (each owns 1 stage of every 4-stage chunk).
#define SPC        112
#define TPB        448
#define NWARPS     (TPB / 32)                  // 14
#define GRID       ((BATCH + SPC - 1) / SPC)   // 293

#define CHUNK_STAGES 4
#define CHUNK_TREES  (CHUNK_STAGES * NCLS)     // 40
#define NCHUNK       (NTREES / CHUNK_TREES)    // 100

// Node word: ((f*SPC) << 12) | j ; x-code word: ((f*SPC) << 12) | c
#define NODE_CHUNK   (CHUNK_TREES * NINT)      // 2520 u32
#define NODE_BYTES   (NODE_CHUNK * 4)          // 10080
#define LEAF_CHUNK   (CHUNK_TREES * NLEAF)     // 2560 f32
#define LEAF_BYTES   (LEAF_CHUNK * 4)          // 10240
#define BUF_BYTES    (NODE_BYTES + LEAF_BYTES) // 20320

#define XS_BYTES    (NFEAT * SPC * 4)          // 57344
#define BUF_OFF(b)  (XS_BYTES + (b) * BUF_BYTES)
#define MBAR_OFF    (XS_BYTES + 2 * BUF_BYTES) // 97984
#define SMEM_TOTAL  (MBAR_OFF + 32)            // 98016

#define SORTN 4096
#define FSEG  3072
#define REP_NODES 511                           // 9-level replicated tree
#define SORT_SMEM  (SORTN * 4)
#define XCODE_SMEM (SORTN * 4 + REP_NODES * 32 * 4)   // 81792 (x2 per SM OK)
#define XCODE_SPLIT 4
#define XCODE_SAMP  (BATCH / XCODE_SPLIT)       // 8192
#define XCODE_ILP   8

#define SCTAS   64
#define STPB    512
#define PER_TH  8
#define NELEMS  (NTREES * NINT)

// Device-global scratch (rebuilt deterministically every launch)
__device__ __align__(16) uint32_t g_nodesQ[NTREES * NINT];
__device__ __align__(16) uint32_t g_xcode[(size_t)NFEAT * BATCH];
__device__ __align__(16) uint32_t g_skey[(size_t)NFEAT * SORTN];
__device__ __align__(16) float    g_xT[(size_t)NFEAT * BATCH];
__device__ int      g_fcount[NFEAT];
__device__ uint64_t g_tpair[(size_t)NFEAT * FSEG];

extern __shared__ char smem_raw[];

__device__ __forceinline__ uint32_t fkey(float v) {
    int b = __float_as_int(v);
    return (uint32_t)(b ^ ((b >> 31) | 0x80000000));
}

__device__ __forceinline__ uint32_t s2u(const void* p) {
    uint32_t a;
    asm("{ .reg .u64 t; cvta.to.shared.u64 t, %1; cvt.u32.u64 %0, t; }"
        : "=r"(a) : "l"(p));
    return a;
}

__device__ __forceinline__ void mbar_init(uint32_t bar, uint32_t cnt) {
    asm volatile("mbarrier.init.shared.b64 [%0], %1;" :: "r"(bar), "r"(cnt) : "memory");
}

__device__ __forceinline__ void mbar_arrive(uint32_t bar) {
    asm volatile("mbarrier.arrive.release.cta.shared::cta.b64 _, [%0];"
                 :: "r"(bar) : "memory");
}

__device__ __forceinline__ void mbar_expect_tx(uint32_t bar, uint32_t bytes) {
    asm volatile("mbarrier.arrive.expect_tx.shared.b64 _, [%0], %1;"
                 :: "r"(bar), "r"(bytes) : "memory");
}

__device__ __forceinline__ void mbar_wait(uint32_t bar, uint32_t parity) {
    uint32_t done;
    asm volatile(
        "{\n\t.reg .pred p;\n\t"
        "mbarrier.try_wait.parity.acquire.cta.shared::cta.b64 p, [%1], %2;\n\t"
        "selp.b32 %0, 1, 0, p;\n\t}"
        : "=r"(done) : "r"(bar), "r"(parity) : "memory");
    while (!done) {
        asm volatile(
            "{\n\t.reg .pred p;\n\t"
            "mbarrier.try_wait.parity.acquire.cta.shared::cta.b64 p, [%1], %2, 0x989680;\n\t"
            "selp.b32 %0, 1, 0, p;\n\t}"
            : "=r"(done) : "r"(bar), "r"(parity) : "memory");
    }
}

__device__ __forceinline__ void bulk_g2s(uint32_t dst, const void* src,
                                         uint32_t bytes, uint32_t bar) {
    asm volatile(
        "cp.async.bulk.shared::cluster.global.mbarrier::complete_tx::bytes "
        "[%0], [%1], %2, [%3];"
        :: "r"(dst), "l"(src), "r"(bytes), "r"(bar) : "memory");
}

// ============================ prep kernels ============================

// Transpose x [BATCH, NFEAT] -> g_xT [NFEAT, BATCH]; block (0,0) zeros counters.
__global__ void __launch_bounds__(256, 2)
prep_transpose_kernel(const float* __restrict__ x)
{
    __shared__ float t[32][33];
    const int tx = threadIdx.x;
    const int ty = threadIdx.y;
    const int flat = ty * 32 + tx;
    const int sBase = blockIdx.x * 32;
    const int fBase = blockIdx.y * 32;

    if (blockIdx.x == 0 && blockIdx.y == 0 && flat < NFEAT)
        g_fcount[flat] = 0;

    #pragma unroll
    for (int rr = ty; rr < 32; rr += 8)
        t[rr][tx] = x[(size_t)(sBase + rr) * NFEAT + fBase + tx];
    __syncthreads();
    #pragma unroll
    for (int rr = ty; rr < 32; rr += 8)
        g_xT[(size_t)(fBase + rr) * BATCH + sBase + tx] = t[tx][rr];
}

__global__ void __launch_bounds__(STPB, 1)
prep_scatter_kernel(const int* __restrict__ features,
                    const float* __restrict__ thresholds)
{
    __shared__ int h[NFEAT];
    __shared__ int hbase[NFEAT];
    const int tid = threadIdx.x;

    for (int i = tid; i < NFEAT; i += STPB) h[i] = 0;
    __syncthreads();

    int      fv[PER_TH];
    uint32_t kv[PER_TH];
    const int base = blockIdx.x * (STPB * PER_TH);

    #pragma unroll
    for (int e = 0; e < PER_TH; e++) {
        int i = base + e * STPB + tid;
        fv[e] = -1;
        if (i < NELEMS) {
            fv[e] = features[i];
            kv[e] = fkey(thresholds[i] + 0.0f);
            atomicAdd(&h[fv[e]], 1);
        }
    }
    __syncthreads();

    for (int i = tid; i < NFEAT; i += STPB) {
        hbase[i] = atomicAdd(&g_fcount[i], h[i]);
        h[i] = 0;
    }
    __syncthreads();

    #pragma unroll
    for (int e = 0; e < PER_TH; e++) {
        if (fv[e] >= 0) {
            int i   = base + e * STPB + tid;
            int off = hbase[fv[e]] + atomicAdd(&h[fv[e]], 1);
            g_tpair[(size_t)fv[e] * FSEG + off] =
                ((uint64_t)kv[e] << 32) | (uint32_t)i;
        }
    }
}

// Per-feature fused bitonic sort (register/warp phases; smem only jj>=128).
__global__ void __launch_bounds__(1024, 1)
prep_sort_kernel()
{
    extern __shared__ char sm4[];
    uint32_t* skey = reinterpret_cast<uint32_t*>(sm4);

    const int f    = blockIdx.x;
    const int tid  = threadIdx.x;
    const int lane = tid & 31;
    const int m    = g_fcount[f];
    const uint64_t* seg = g_tpair + (size_t)f * FSEG;
    const uint32_t prefix = (uint32_t)(f * SPC) << 12;

    for (int p = tid; p < SORTN; p += 1024)
        skey[p] = (p < m) ? (uint32_t)(seg[p] >> 32) : 0xFFFFFFFFu;
    __syncthreads();

    uint32_t v[4];

    auto warp_phase = [&](int jj, int k) {
        if (jj >= 4) {
            const int lm = jj >> 2;
            #pragma unroll
            for (int e = 0; e < 4; e++) {
                uint32_t o = __shfl_xor_sync(0xffffffffu, v[e], lm);
                int  i     = (tid << 2) + e;
                bool up    = ((i & k) == 0);
                bool lower = ((lane & lm) == 0);
                uint32_t mn = min(v[e], o), mx = max(v[e], o);
                v[e] = (lower == up) ? mn : mx;
            }
        } else {
            #pragma unroll
            for (int e = 0; e < 4; e++) {
                int pe = e ^ jj;
                if (pe > e) {
                    int  i  = (tid << 2) + e;
                    bool up = ((i & k) == 0);
                    uint32_t a = v[e], b = v[pe];
                    if ((a > b) == up) { v[e] = b; v[pe] = a; }
                }
            }
        }
    };

    #pragma unroll
    for (int e = 0; e < 4; e++) v[e] = skey[(tid << 2) + e];
    for (int k = 2; k <= 128; k <<= 1)
        for (int jj = k >> 1; jj >= 1; jj >>= 1)
            warp_phase(jj, k);
    #pragma unroll
    for (int e = 0; e < 4; e++) skey[(tid << 2) + e] = v[e];
    __syncthreads();

    for (int k = 256; k <= SORTN; k <<= 1) {
        for (int jj = k >> 1; jj >= 128; jj >>= 1) {
            for (int i = tid; i < SORTN; i += 1024) {
                int p = i ^ jj;
                if (p > i) {
                    uint32_t a = skey[i], b = skey[p];
                    bool up = ((i & k) == 0);
                    if ((a > b) == up) { skey[i] = b; skey[p] = a; }
                }
            }
            __syncthreads();
        }
        #pragma unroll
        for (int e = 0; e < 4; e++) v[e] = skey[(tid << 2) + e];
        for (int jj = 64; jj >= 1; jj >>= 1)
            warp_phase(jj, k);
        #pragma unroll
        for (int e = 0; e < 4; e++) skey[(tid << 2) + e] = v[e];
        __syncthreads();
    }

    for (int p = tid; p < m; p += 1024) {
        uint64_t pr  = seg[p];
        uint32_t key = (uint32_t)(pr >> 32);
        uint32_t id  = (uint32_t)(pr & 0xFFFFFFFFull);
        int pos = 0;
        #pragma unroll
        for (int w = SORTN >> 1; w >= 1; w >>= 1)
            if (skey[pos + w - 1] <= key) pos += w;
        g_nodesQ[id] = prefix | (uint32_t)pos;
    }

    for (int p = tid; p < SORTN; p += 1024)
        g_skey[(size_t)f * SORTN + p] = skey[p];
}

// 4 CTAs per feature; 8 chains/thread; 9-level bank-replicated tree +
// 3-level level-major tail.
__global__ void __launch_bounds__(1024, 1)
prep_xcode_kernel()
{
    extern __shared__ char sm4[];
    uint32_t* skey = reinterpret_cast<uint32_t*>(sm4);
    uint32_t* rep  = reinterpret_cast<uint32_t*>(sm4 + SORTN * 4);

    const int f    = blockIdx.x >> 2;
    const int part = blockIdx.x & 3;
    const int tid  = threadIdx.x;
    const int lane = tid & 31;
    const uint32_t prefix = (uint32_t)(f * SPC) << 12;

    for (int p = tid; p < SORTN; p += 1024)
        skey[p] = g_skey[(size_t)f * SORTN + p];
    __syncthreads();

    // 9-level tree: level L has 2^L nodes, pivot stride w = 2048 >> L (L<=8).
    for (int i = tid; i < REP_NODES * 32; i += 1024) {
        int nb = i >> 5;
        int L  = 31 - __clz(nb + 1);
        int q  = (nb + 1) - (1 << L);
        int w  = 2048 >> L;
        rep[i] = skey[(2 * q + 1) * w - 1];
    }
    __syncthreads();

    const int sBase = part * XCODE_SAMP;
    uint32_t key[XCODE_ILP];
    int      qn [XCODE_ILP];

    #pragma unroll
    for (int i = 0; i < XCODE_ILP; i++) {
        int s  = sBase + i * 1024 + tid;
        key[i] = fkey(g_xT[(size_t)f * BATCH + s] + 0.0f);
        qn[i]  = 0;
    }
    #pragma unroll
    for (int L = 0; L < 9; L++) {               // level-major, conflict-free
        #pragma unroll
        for (int i = 0; i < XCODE_ILP; i++) {
            uint32_t tk = rep[(((1 << L) - 1 + qn[i]) << 5) + lane];
            qn[i] = 2 * qn[i] + (tk < key[i]);
        }
    }
    #pragma unroll
    for (int i = 0; i < XCODE_ILP; i++) qn[i] <<= 3;   // 8-element window
    {   // 3-level tail, level-major across chains (8-way MLP)
        #pragma unroll
        for (int i = 0; i < XCODE_ILP; i++)
            if (skey[qn[i] + 3] < key[i]) qn[i] += 4;
        #pragma unroll
        for (int i = 0; i < XCODE_ILP; i++)
            if (skey[qn[i] + 1] < key[i]) qn[i] += 2;
        #pragma unroll
        for (int i = 0; i < XCODE_ILP; i++)
            if (skey[qn[i]] < key[i]) qn[i] += 1;
    }
    #pragma unroll
    for (int i = 0; i < XCODE_ILP; i++) {
        int s = sBase + i * 1024 + tid;
        g_xcode[(size_t)f * BATCH + s] = prefix | (uint32_t)qn[i];
    }
}

// ============================ main kernel ============================

__global__ void __launch_bounds__(TPB, 2)
gbt_forest_kernel(const float* __restrict__ leaf_values,
                  const float* __restrict__ init_out,
                  float*       __restrict__ out)
{
    uint32_t* xsw = reinterpret_cast<uint32_t*>(smem_raw);
    uint64_t* mbar = reinterpret_cast<uint64_t*>(smem_raw + MBAR_OFF);

    const int tid  = threadIdx.x;
    const int lane = tid & 31;
    const int q    = tid / SPC;
    const int r    = tid - q * SPC;
    const int base = blockIdx.x * SPC;

    const uint32_t full0  = s2u(&mbar[0]);
    const uint32_t full1  = s2u(&mbar[1]);
    const uint32_t empty0 = s2u(&mbar[2]);
    const uint32_t empty1 = s2u(&mbar[3]);
    const uint32_t dst0   = s2u(smem_raw + BUF_OFF(0));
    const uint32_t dst1   = s2u(smem_raw + BUF_OFF(1));

    const uint32_t* gN = g_nodesQ;

    if (tid == 0) {
        mbar_init(full0, 1);
        mbar_init(full1, 1);
        mbar_init(empty0, NWARPS);
        mbar_init(empty1, NWARPS);
        asm volatile("fence.proxy.async.shared::cta;" ::: "memory");
        mbar_expect_tx(full0, BUF_BYTES);
        bulk_g2s(dst0,              gN,                       NODE_BYTES, full0);
        bulk_g2s(dst0 + NODE_BYTES, leaf_values,              LEAF_BYTES, full0);
        mbar_expect_tx(full1, BUF_BYTES);
        bulk_g2s(dst1,              gN + NODE_CHUNK,          NODE_BYTES, full1);
        bulk_g2s(dst1 + NODE_BYTES, leaf_values + LEAF_CHUNK, LEAF_BYTES, full1);
    }

    for (int ii = tid; ii < NFEAT * SPC; ii += TPB) {
        int ff = ii / SPC;
        int rr = ii - ff * SPC;
        int gs = min(base + rr, BATCH - 1);
        xsw[ff * SPC + rr] = g_xcode[(size_t)ff * BATCH + gs];
    }
    __syncthreads();

    float acc[NCLS];
    #pragma unroll
    for (int k = 0; k < NCLS; k++) acc[k] = 0.0f;

    const uint32_t* xcol = xsw + r;

    for (int c = 0; c < NCHUNK; c++) {
        const int b  = c & 1;
        const int ph = (c >> 1) & 1;
        const uint32_t fullB  = b ? full1 : full0;
        const uint32_t emptyB = b ? empty1 : empty0;
        const char* pCur = smem_raw + BUF_OFF(b);

        mbar_wait(fullB, ph);

        const uint32_t* nodeB = reinterpret_cast<const uint32_t*>(pCur);
        const float*    leafB = reinterpret_cast<const float*>(pCur + NODE_BYTES);

        // 5 pairs of trees; 2 named scalar chains per pair -> 2x LDS MLP.
        #pragma unroll
        for (int kp = 0; kp < NCLS / 2; kp++) {
            const int tj0 = q * NCLS + 2 * kp;
            const uint32_t* nt0 = nodeB + tj0 * NINT;
            const uint32_t* nt1 = nt0 + NINT;
            uint32_t i0 = 0, i1 = 0;
            #pragma unroll
            for (int l = 0; l < 6; l++) {
                uint32_t n0 = nt0[i0];
                uint32_t n1 = nt1[i1];
                uint32_t c0 = xcol[n0 >> 12];
                uint32_t c1 = xcol[n1 >> 12];
                i0 = 2 * i0 + 1 + (c0 >= n0);
                i1 = 2 * i1 + 1 + (c1 >= n1);
            }
            acc[2 * kp]     += leafB[tj0 * NLEAF       + ((int)i0 - NINT)];
            acc[2 * kp + 1] += leafB[(tj0 + 1) * NLEAF + ((int)i1 - NINT)];
        }

        __syncwarp();
        if (lane == 0) mbar_arrive(emptyB);

        if (tid == 0 && c + 2 < NCHUNK) {
            mbar_wait(emptyB, ph);
            asm volatile("fence.proxy.async.shared::cta;" ::: "memory");
            const int nc = c + 2;
            const uint32_t dstB = b ? dst1 : dst0;
            mbar_expect_tx(fullB, BUF_BYTES);
            bulk_g2s(dstB,              gN + (size_t)nc * NODE_CHUNK, NODE_BYTES, fullB);
            bulk_g2s(dstB + NODE_BYTES, leaf_values + (size_t)nc * LEAF_CHUNK,
                     LEAF_BYTES, fullB);
        }
    }

    __syncthreads();

    float* red = reinterpret_cast<float*>(smem_raw);
    if (q > 0) {
        #pragma unroll
        for (int k = 0; k < NCLS; k++)
            red[((q - 1) * SPC + r) * NCLS + k] = acc[k];
    }
    __syncthreads();

    if (q == 0 && base + r < BATCH) {
        const int sample = base + r;
        #pragma unroll
        for (int k = 0; k < NCLS; k++) {
            float v = acc[k]
                    + red[(0 * SPC + r) * NCLS + k]
                    + red[(1 * SPC + r) * NCLS + k]
                    + red[(2 * SPC + r) * NCLS + k];
            out[(size_t)sample * NCLS + k] = __ldg(init_out + k) + LR * v;
        }
    }
}

extern "C" void kernel_launch(void* const* d_in, const int* in_sizes, int n_in,
                              void* d_out, int out_size)
{
    (void)in_sizes; (void)n_in; (void)out_size;

    const float* x           = (const float*)d_in[0];
    const int*   features    = (const int*)  d_in[1];
    const float* thresholds  = (const float*)d_in[2];
    const float* leaf_values = (const float*)d_in[3];
    const float* init_out    = (const float*)d_in[4];
    float*       out         = (float*)d_out;

    static bool attr_set = false;
    if (!attr_set) {
        cudaFuncSetAttribute(gbt_forest_kernel,
                             cudaFuncAttributeMaxDynamicSharedMemorySize, SMEM_TOTAL);
        cudaFuncSetAttribute(prep_sort_kernel,
                             cudaFuncAttributeMaxDynamicSharedMemorySize, SORT_SMEM);
        cudaFuncSetAttribute(prep_xcode_kernel,
                             cudaFuncAttributeMaxDynamicSharedMemorySize, XCODE_SMEM);
        attr_set = true;
    }

    {
        dim3 tb(32, 8);
        dim3 tg(BATCH / 32, NFEAT / 32);
        prep_transpose_kernel<<<tg, tb>>>(x);   // also zeros g_fcount
    }
    prep_scatter_kernel<<<SCTAS, STPB>>>(features, thresholds);
    prep_sort_kernel<<<NFEAT, 1024, SORT_SMEM>>>();
    prep_xcode_kernel<<<NFEAT * XCODE_SPLIT, 1024, XCODE_SMEM>>>();
    gbt_forest_kernel<<<GRID, TPB, SMEM_TOTAL>>>(leaf_values, init_out, out);
}

// round 16
// speedup vs baseline: 1.4865x; 1.0009x over previous
#include <cuda_runtime.h>
#include <cstdint>

// Problem constants
#define BATCH      32768
#define NFEAT      128
#define NTREES     4000
#define NINT       63
#define NLEAF      64
#define NCLS       10
#define LR         0.1f

// Main-kernel tiling: TWO CTAs per SM. 112 samples/CTA, 448 threads =
// 4 threads per sample (each owns 1 stage of every 4-stage chunk).
#define SPC        112
#define TPB        448
#define NWARPS     (TPB / 32)                  // 14
#define GRID       ((BATCH + SPC - 1) / SPC)   // 293

#define CHUNK_STAGES 4
#define CHUNK_TREES  (CHUNK_STAGES * NCLS)     // 40
#define NCHUNK       (NTREES / CHUNK_TREES)    // 100

// Node word: ((f*SPC) << 12) | j ; x-code word: ((f*SPC) << 12) | c
#define NODE_CHUNK   (CHUNK_TREES * NINT)      // 2520 u32
#define NODE_BYTES   (NODE_CHUNK * 4)          // 10080
#define LEAF_CHUNK   (CHUNK_TREES * NLEAF)     // 2560 f32
#define LEAF_BYTES   (LEAF_CHUNK * 4)          // 10240
#define BUF_BYTES    (NODE_BYTES + LEAF_BYTES) // 20320

#define XS_BYTES    (NFEAT * SPC * 4)          // 57344
#define BUF_OFF(b)  (XS_BYTES + (b) * BUF_BYTES)
#define MBAR_OFF    (XS_BYTES + 2 * BUF_BYTES) // 97984
#define SMEM_TOTAL  (MBAR_OFF + 32)            // 98016

#define SORTN 4096
#define FSEG  3072
#define REP_NODES 511
#define SORT_SMEM  (SORTN * 4)
#define XCODE_SMEM (SORTN * 4 + REP_NODES * 32 * 4)   // 81792
#define XCODE_SPLIT 4
#define XCODE_SAMP  (BATCH / XCODE_SPLIT)       // 8192
#define XCODE_ILP   8

#define SCTAS   64
#define STPB    512
#define PER_TH  8
#define NELEMS  (NTREES * NINT)

// Device-global scratch (rebuilt deterministically every launch)
__device__ __align__(16) uint32_t g_nodesQ[NTREES * NINT];
__device__ __align__(16) uint32_t g_xcode[(size_t)NFEAT * BATCH];
__device__ __align__(16) uint32_t g_skey[(size_t)NFEAT * SORTN];
__device__ __align__(16) float    g_xT[(size_t)NFEAT * BATCH];
__device__ int      g_fcount[NFEAT];
__device__ uint64_t g_tpair[(size_t)NFEAT * FSEG];

extern __shared__ char smem_raw[];

__device__ __forceinline__ uint32_t fkey(float v) {
    int b = __float_as_int(v);
    return (uint32_t)(b ^ ((b >> 31) | 0x80000000));
}

__device__ __forceinline__ uint32_t s2u(const void* p) {
    uint32_t a;
    asm("{ .reg .u64 t; cvta.to.shared.u64 t, %1; cvt.u32.u64 %0, t; }"
        : "=r"(a) : "l"(p));
    return a;
}

__device__ __forceinline__ void mbar_init(uint32_t bar, uint32_t cnt) {
    asm volatile("mbarrier.init.shared.b64 [%0], %1;" :: "r"(bar), "r"(cnt) : "memory");
}

__device__ __forceinline__ void mbar_arrive(uint32_t bar) {
    asm volatile("mbarrier.arrive.release.cta.shared::cta.b64 _, [%0];"
                 :: "r"(bar) : "memory");
}

__device__ __forceinline__ void mbar_expect_tx(uint32_t bar, uint32_t bytes) {
    asm volatile("mbarrier.arrive.expect_tx.shared.b64 _, [%0], %1;"
                 :: "r"(bar), "r"(bytes) : "memory");
}

__device__ __forceinline__ void mbar_wait(uint32_t bar, uint32_t parity) {
    uint32_t done;
    asm volatile(
        "{\n\t.reg .pred p;\n\t"
        "mbarrier.try_wait.parity.acquire.cta.shared::cta.b64 p, [%1], %2;\n\t"
        "selp.b32 %0, 1, 0, p;\n\t}"
        : "=r"(done) : "r"(bar), "r"(parity) : "memory");
    while (!done) {
        asm volatile(
            "{\n\t.reg .pred p;\n\t"
            "mbarrier.try_wait.parity.acquire.cta.shared::cta.b64 p, [%1], %2, 0x989680;\n\t"
            "selp.b32 %0, 1, 0, p;\n\t}"
            : "=r"(done) : "r"(bar), "r"(parity) : "memory");
    }
}

__device__ __forceinline__ void bulk_g2s(uint32_t dst, const void* src,
                                         uint32_t bytes, uint32_t bar) {
    asm volatile(
        "cp.async.bulk.shared::cluster.global.mbarrier::complete_tx::bytes "
        "[%0], [%1], %2, [%3];"
        :: "r"(dst), "l"(src), "r"(bytes), "r"(bar) : "memory");
}

// ============================ prep kernels ============================

__global__ void __launch_bounds__(256, 2)
prep_transpose_kernel(const float* __restrict__ x)
{
    __shared__ float t[32][33];
    const int tx = threadIdx.x;
    const int ty = threadIdx.y;
    const int flat = ty * 32 + tx;
    const int sBase = blockIdx.x * 32;
    const int fBase = blockIdx.y * 32;

    if (blockIdx.x == 0 && blockIdx.y == 0 && flat < NFEAT)
        g_fcount[flat] = 0;

    #pragma unroll
    for (int rr = ty; rr < 32; rr += 8)
        t[rr][tx] = x[(size_t)(sBase + rr) * NFEAT + fBase + tx];
    __syncthreads();
    #pragma unroll
    for (int rr = ty; rr < 32; rr += 8)
        g_xT[(size_t)(fBase + rr) * BATCH + sBase + tx] = t[tx][rr];
}

__global__ void __launch_bounds__(STPB, 1)
prep_scatter_kernel(const int* __restrict__ features,
                    const float* __restrict__ thresholds)
{
    __shared__ int h[NFEAT];
    __shared__ int hbase[NFEAT];
    const int tid = threadIdx.x;

    for (int i = tid; i < NFEAT; i += STPB) h[i] = 0;
    __syncthreads();

    int      fv[PER_TH];
    uint32_t kv[PER_TH];
    const int base = blockIdx.x * (STPB * PER_TH);

    #pragma unroll
    for (int e = 0; e < PER_TH; e++) {
        int i = base + e * STPB + tid;
        fv[e] = -1;
        if (i < NELEMS) {
            fv[e] = features[i];
            kv[e] = fkey(thresholds[i] + 0.0f);
            atomicAdd(&h[fv[e]], 1);
        }
    }
    __syncthreads();

    for (int i = tid; i < NFEAT; i += STPB) {
        hbase[i] = atomicAdd(&g_fcount[i], h[i]);
        h[i] = 0;
    }
    __syncthreads();

    #pragma unroll
    for (int e = 0; e < PER_TH; e++) {
        if (fv[e] >= 0) {
            int i   = base + e * STPB + tid;
            int off = hbase[fv[e]] + atomicAdd(&h[fv[e]], 1);
            g_tpair[(size_t)fv[e] * FSEG + off] =
                ((uint64_t)kv[e] << 32) | (uint32_t)i;
        }
    }
}

__global__ void __launch_bounds__(1024, 1)
prep_sort_kernel()
{
    extern __shared__ char sm4[];
    uint32_t* skey = reinterpret_cast<uint32_t*>(sm4);

    const int f    = blockIdx.x;
    const int tid  = threadIdx.x;
    const int lane = tid & 31;
    const int m    = g_fcount[f];
    const uint64_t* seg = g_tpair + (size_t)f * FSEG;
    const uint32_t prefix = (uint32_t)(f * SPC) << 12;

    for (int p = tid; p < SORTN; p += 1024)
        skey[p] = (p < m) ? (uint32_t)(seg[p] >> 32) : 0xFFFFFFFFu;
    __syncthreads();

    uint32_t v[4];

    auto warp_phase = [&](int jj, int k) {
        if (jj >= 4) {
            const int lm = jj >> 2;
            #pragma unroll
            for (int e = 0; e < 4; e++) {
                uint32_t o = __shfl_xor_sync(0xffffffffu, v[e], lm);
                int  i     = (tid << 2) + e;
                bool up    = ((i & k) == 0);
                bool lower = ((lane & lm) == 0);
                uint32_t mn = min(v[e], o), mx = max(v[e], o);
                v[e] = (lower == up) ? mn : mx;
            }
        } else {
            #pragma unroll
            for (int e = 0; e < 4; e++) {
                int pe = e ^ jj;
                if (pe > e) {
                    int  i  = (tid << 2) + e;
                    bool up = ((i & k) == 0);
                    uint32_t a = v[e], b = v[pe];
                    if ((a > b) == up) { v[e] = b; v[pe] = a; }
                }
            }
        }
    };

    #pragma unroll
    for (int e = 0; e < 4; e++) v[e] = skey[(tid << 2) + e];
    for (int k = 2; k <= 128; k <<= 1)
        for (int jj = k >> 1; jj >= 1; jj >>= 1)
            warp_phase(jj, k);
    #pragma unroll
    for (int e = 0; e < 4; e++) skey[(tid << 2) + e] = v[e];
    __syncthreads();

    for (int k = 256; k <= SORTN; k <<= 1) {
        for (int jj = k >> 1; jj >= 128; jj >>= 1) {
            for (int i = tid; i < SORTN; i += 1024) {
                int p = i ^ jj;
                if (p > i) {
                    uint32_t a = skey[i], b = skey[p];
                    bool up = ((i & k) == 0);
                    if ((a > b) == up) { skey[i] = b; skey[p] = a; }
                }
            }
            __syncthreads();
        }
        #pragma unroll
        for (int e = 0; e < 4; e++) v[e] = skey[(tid << 2) + e];
        for (int jj = 64; jj >= 1; jj >>= 1)
            warp_phase(jj, k);
        #pragma unroll
        for (int e = 0; e < 4; e++) skey[(tid << 2) + e] = v[e];
        __syncthreads();
    }

    for (int p = tid; p < m; p += 1024) {
        uint64_t pr  = seg[p];
        uint32_t key = (uint32_t)(pr >> 32);
        uint32_t id  = (uint32_t)(pr & 0xFFFFFFFFull);
        int pos = 0;
        #pragma unroll
        for (int w = SORTN >> 1; w >= 1; w >>= 1)
            if (skey[pos + w - 1] <= key) pos += w;
        g_nodesQ[id] = prefix | (uint32_t)pos;
    }

    for (int p = tid; p < SORTN; p += 1024)
        g_skey[(size_t)f * SORTN + p] = skey[p];
}

__global__ void __launch_bounds__(1024, 1)
prep_xcode_kernel()
{
    extern __shared__ char sm4[];
    uint32_t* skey = reinterpret_cast<uint32_t*>(sm4);
    uint32_t* rep  = reinterpret_cast<uint32_t*>(sm4 + SORTN * 4);

    const int f    = blockIdx.x >> 2;
    const int part = blockIdx.x & 3;
    const int tid  = threadIdx.x;
    const int lane = tid & 31;
    const uint32_t prefix = (uint32_t)(f * SPC) << 12;

    for (int p = tid; p < SORTN; p += 1024)
        skey[p] = g_skey[(size_t)f * SORTN + p];
    __syncthreads();

    for (int i = tid; i < REP_NODES * 32; i += 1024) {
        int nb = i >> 5;
        int L  = 31 - __clz(nb + 1);
        int q  = (nb + 1) - (1 << L);
        int w  = 2048 >> L;
        rep[i] = skey[(2 * q + 1) * w - 1];
    }
    __syncthreads();

    const int sBase = part * XCODE_SAMP;
    uint32_t key[XCODE_ILP];
    int      qn [XCODE_ILP];

    #pragma unroll
    for (int i = 0; i < XCODE_ILP; i++) {
        int s  = sBase + i * 1024 + tid;
        key[i] = fkey(g_xT[(size_t)f * BATCH + s] + 0.0f);
        qn[i]  = 0;
    }
    #pragma unroll
    for (int L = 0; L < 9; L++) {
        #pragma unroll
        for (int i = 0; i < XCODE_ILP; i++) {
            uint32_t tk = rep[(((1 << L) - 1 + qn[i]) << 5) + lane];
            qn[i] = 2 * qn[i] + (tk < key[i]);
        }
    }
    #pragma unroll
    for (int i = 0; i < XCODE_ILP; i++) qn[i] <<= 3;
    {
        #pragma unroll
        for (int i = 0; i < XCODE_ILP; i++)
            if (skey[qn[i] + 3] < key[i]) qn[i] += 4;
        #pragma unroll
        for (int i = 0; i < XCODE_ILP; i++)
            if (skey[qn[i] + 1] < key[i]) qn[i] += 2;
        #pragma unroll
        for (int i = 0; i < XCODE_ILP; i++)
            if (skey[qn[i]] < key[i]) qn[i] += 1;
    }
    #pragma unroll
    for (int i = 0; i < XCODE_ILP; i++) {
        int s = sBase + i * 1024 + tid;
        g_xcode[(size_t)f * BATCH + s] = prefix | (uint32_t)qn[i];
    }
}

// ============================ main kernel ============================

__global__ void __launch_bounds__(TPB, 2)
gbt_forest_kernel(const float* __restrict__ leaf_values,
                  const float* __restrict__ init_out,
                  float*       __restrict__ out)
{
    uint32_t* xsw = reinterpret_cast<uint32_t*>(smem_raw);
    uint64_t* mbar = reinterpret_cast<uint64_t*>(smem_raw + MBAR_OFF);

    const int tid  = threadIdx.x;
    const int lane = tid & 31;
    const int q    = tid / SPC;
    const int r    = tid - q * SPC;
    const int base = blockIdx.x * SPC;

    const uint32_t full0  = s2u(&mbar[0]);
    const uint32_t full1  = s2u(&mbar[1]);
    const uint32_t empty0 = s2u(&mbar[2]);
    const uint32_t empty1 = s2u(&mbar[3]);
    const uint32_t dst0   = s2u(smem_raw + BUF_OFF(0));
    const uint32_t dst1   = s2u(smem_raw + BUF_OFF(1));

    const uint32_t* gN = g_nodesQ;

    if (tid == 0) {
        mbar_init(full0, 1);
        mbar_init(full1, 1);
        mbar_init(empty0, NWARPS);
        mbar_init(empty1, NWARPS);
        asm volatile("fence.proxy.async.shared::cta;" ::: "memory");
        mbar_expect_tx(full0, BUF_BYTES);
        bulk_g2s(dst0,              gN,                       NODE_BYTES, full0);
        bulk_g2s(dst0 + NODE_BYTES, leaf_values,              LEAF_BYTES, full0);
        mbar_expect_tx(full1, BUF_BYTES);
        bulk_g2s(dst1,              gN + NODE_CHUNK,          NODE_BYTES, full1);
        bulk_g2s(dst1 + NODE_BYTES, leaf_values + LEAF_CHUNK, LEAF_BYTES, full1);
    }

    for (int ii = tid; ii < NFEAT * SPC; ii += TPB) {
        int ff = ii / SPC;
        int rr = ii - ff * SPC;
        int gs = min(base + rr, BATCH - 1);
        xsw[ff * SPC + rr] = g_xcode[(size_t)ff * BATCH + gs];
    }
    __syncthreads();

    float acc[NCLS];
    #pragma unroll
    for (int k = 0; k < NCLS; k++) acc[k] = 0.0f;

    const uint32_t* xcol = xsw + r;

    for (int c = 0; c < NCHUNK; c++) {
        const int b  = c & 1;
        const int ph = (c >> 1) & 1;
        const uint32_t fullB  = b ? full1 : full0;
        const uint32_t emptyB = b ? empty1 : empty0;
        const char* pCur = smem_raw + BUF_OFF(b);

        mbar_wait(fullB, ph);

        const uint32_t* nodeB = reinterpret_cast<const uint32_t*>(pCur);
        const float*    leafB = reinterpret_cast<const float*>(pCur + NODE_BYTES);

        // 2 groups of 5 trees; 5 named scalar chains per group -> 5x LDS MLP.
        #pragma unroll
        for (int g = 0; g < 2; g++) {
            const int tjb = q * NCLS + g * 5;
            const uint32_t* nt0 = nodeB + tjb * NINT;
            const uint32_t* nt1 = nt0 + NINT;
            const uint32_t* nt2 = nt1 + NINT;
            const uint32_t* nt3 = nt2 + NINT;
            const uint32_t* nt4 = nt3 + NINT;
            uint32_t i0 = 0, i1 = 0, i2 = 0, i3 = 0, i4 = 0;
            #pragma unroll
            for (int l = 0; l < 6; l++) {
                uint32_t n0 = nt0[i0];
                uint32_t n1 = nt1[i1];
                uint32_t n2 = nt2[i2];
                uint32_t n3 = nt3[i3];
                uint32_t n4 = nt4[i4];
                uint32_t c0 = xcol[n0 >> 12];
                uint32_t c1 = xcol[n1 >> 12];
                uint32_t c2 = xcol[n2 >> 12];
                uint32_t c3 = xcol[n3 >> 12];
                uint32_t c4 = xcol[n4 >> 12];
                i0 = 2 * i0 + 1 + (c0 >= n0);
                i1 = 2 * i1 + 1 + (c1 >= n1);
                i2 = 2 * i2 + 1 + (c2 >= n2);
                i3 = 2 * i3 + 1 + (c3 >= n3);
                i4 = 2 * i4 + 1 + (c4 >= n4);
            }
            acc[g * 5 + 0] += leafB[(tjb + 0) * NLEAF + ((int)i0 - NINT)];
            acc[g * 5 + 1] += leafB[(tjb + 1) * NLEAF + ((int)i1 - NINT)];
            acc[g * 5 + 2] += leafB[(tjb + 2) * NLEAF + ((int)i2 - NINT)];
            acc[g * 5 + 3] += leafB[(tjb + 3) * NLEAF + ((int)i3 - NINT)];
            acc[g * 5 + 4] += leafB[(tjb + 4) * NLEAF + ((int)i4 - NINT)];
        }

        __syncwarp();
        if (lane == 0) mbar_arrive(emptyB);

        if (tid == 0 && c + 2 < NCHUNK) {
            mbar_wait(emptyB, ph);
            asm volatile("fence.proxy.async.shared::cta;" ::: "memory");
            const int nc = c + 2;
            const uint32_t dstB = b ? dst1 : dst0;
            mbar_expect_tx(fullB, BUF_BYTES);
            bulk_g2s(dstB,              gN + (size_t)nc * NODE_CHUNK, NODE_BYTES, fullB);
            bulk_g2s(dstB + NODE_BYTES, leaf_values + (size_t)nc * LEAF_CHUNK,
                     LEAF_BYTES, fullB);
        }
    }

    __syncthreads();

    float* red = reinterpret_cast<float*>(smem_raw);
    if (q > 0) {
        #pragma unroll
        for (int k = 0; k < NCLS; k++)
            red[((q - 1) * SPC + r) * NCLS + k] = acc[k];
    }
    __syncthreads();

    if (q == 0 && base + r < BATCH) {
        const int sample = base + r;
        #pragma unroll
        for (int k = 0; k < NCLS; k++) {
            float v = acc[k]
                    + red[(0 * SPC + r) * NCLS + k]
                    + red[(1 * SPC + r) * NCLS + k]
                    + red[(2 * SPC + r) * NCLS + k];
            out[(size_t)sample * NCLS + k] = __ldg(init_out + k) + LR * v;
        }
    }
}

extern "C" void kernel_launch(void* const* d_in, const int* in_sizes, int n_in,
                              void* d_out, int out_size)
{
    (void)in_sizes; (void)n_in; (void)out_size;

    const float* x           = (const float*)d_in[0];
    const int*   features    = (const int*)  d_in[1];
    const float* thresholds  = (const float*)d_in[2];
    const float* leaf_values = (const float*)d_in[3];
    const float* init_out    = (const float*)d_in[4];
    float*       out         = (float*)d_out;

    static bool attr_set = false;
    if (!attr_set) {
        cudaFuncSetAttribute(gbt_forest_kernel,
                             cudaFuncAttributeMaxDynamicSharedMemorySize, SMEM_TOTAL);
        cudaFuncSetAttribute(prep_sort_kernel,
                             cudaFuncAttributeMaxDynamicSharedMemorySize, SORT_SMEM);
        cudaFuncSetAttribute(prep_xcode_kernel,
                             cudaFuncAttributeMaxDynamicSharedMemorySize, XCODE_SMEM);
        attr_set = true;
    }

    {
        dim3 tb(32, 8);
        dim3 tg(BATCH / 32, NFEAT / 32);
        prep_transpose_kernel<<<tg, tb>>>(x);   // also zeros g_fcount
    }
    prep_scatter_kernel<<<SCTAS, STPB>>>(features, thresholds);
    prep_sort_kernel<<<NFEAT, 1024, SORT_SMEM>>>();
    prep_xcode_kernel<<<NFEAT * XCODE_SPLIT, 1024, XCODE_SMEM>>>();
    gbt_forest_kernel<<<GRID, TPB, SMEM_TOTAL>>>(leaf_values, init_out, out);
}

// round 17
// speedup vs baseline: 1.4962x; 1.0065x over previous
#include <cuda_runtime.h>
#include <cstdint>

// Problem constants
#define BATCH      32768
#define NFEAT      128
#define NTREES     4000
#define NINT       63
#define NLEAF      64
#define NCLS       10
#define LR         0.1f

// Main-kernel tiling: TWO CTAs per SM. 112 samples/CTA, 448 threads =
// 4 threads per sample (each owns 1 stage of every 4-stage chunk).
#define SPC        112
#define TPB        448
#define NWARPS     (TPB / 32)                  // 14
#define GRID       ((BATCH + SPC - 1) / SPC)   // 293

#define CHUNK_STAGES 4
#define CHUNK_TREES  (CHUNK_STAGES * NCLS)     // 40
#define NCHUNK       (NTREES / CHUNK_TREES)    // 100

// Node word: ((f*SPC) << 12) | j ; x-code smem word: ((f*SPC) << 12) | c
#define NODE_CHUNK   (CHUNK_TREES * NINT)      // 2520 u32
#define NODE_BYTES   (NODE_CHUNK * 4)          // 10080
#define LEAF_CHUNK   (CHUNK_TREES * NLEAF)     // 2560 f32
#define LEAF_BYTES   (LEAF_CHUNK * 4)          // 10240
#define BUF_BYTES    (NODE_BYTES + LEAF_BYTES) // 20320

#define XS_BYTES    (NFEAT * SPC * 4)          // 57344
#define BUF_OFF(b)  (XS_BYTES + (b) * BUF_BYTES)
#define MBAR_OFF    (XS_BYTES + 2 * BUF_BYTES) // 97984
#define SMEM_TOTAL  (MBAR_OFF + 32)            // 98016

#define SORTN 4096
#define FSEG  3072
#define REP_NODES 511
#define SORT_SMEM  (SORTN * 4)
#define XCODE_SMEM (SORTN * 4 + REP_NODES * 32 * 4)   // 81792
#define XCODE_SPLIT 4
#define XCODE_SAMP  (BATCH / XCODE_SPLIT)       // 8192
#define XCODE_ILP   8

// Fused front kernel: 4096 transpose blocks + 128 scatter blocks, 256 thr.
#define TR_BLOCKS  ((BATCH / 32) * (NFEAT / 32))   // 4096
#define SC_BLOCKS  128
#define SC_TPB     256
#define SC_PER_TH  8                                // 128*256*8 = 262144
#define NELEMS     (NTREES * NINT)                  // 252000

// Device-global scratch (rebuilt deterministically every launch)
__device__ __align__(16) uint32_t g_nodesQ[NTREES * NINT];
__device__ __align__(16) uint16_t g_xcode[(size_t)NFEAT * BATCH];   // 12-bit codes
__device__ __align__(16) uint32_t g_skey[(size_t)NFEAT * SORTN];
__device__ __align__(16) float    g_xT[(size_t)NFEAT * BATCH];
__device__ int      g_fcount[NFEAT];
__device__ uint64_t g_tpair[(size_t)NFEAT * FSEG];

extern __shared__ char smem_raw[];

__device__ __forceinline__ uint32_t fkey(float v) {
    int b = __float_as_int(v);
    return (uint32_t)(b ^ ((b >> 31) | 0x80000000));
}

__device__ __forceinline__ uint32_t s2u(const void* p) {
    uint32_t a;
    asm("{ .reg .u64 t; cvta.to.shared.u64 t, %1; cvt.u32.u64 %0, t; }"
        : "=r"(a) : "l"(p));
    return a;
}

__device__ __forceinline__ void mbar_init(uint32_t bar, uint32_t cnt) {
    asm volatile("mbarrier.init.shared.b64 [%0], %1;" :: "r"(bar), "r"(cnt) : "memory");
}

__device__ __forceinline__ void mbar_arrive(uint32_t bar) {
    asm volatile("mbarrier.arrive.release.cta.shared::cta.b64 _, [%0];"
                 :: "r"(bar) : "memory");
}

__device__ __forceinline__ void mbar_expect_tx(uint32_t bar, uint32_t bytes) {
    asm volatile("mbarrier.arrive.expect_tx.shared.b64 _, [%0], %1;"
                 :: "r"(bar), "r"(bytes) : "memory");
}

__device__ __forceinline__ void mbar_wait(uint32_t bar, uint32_t parity) {
    uint32_t done;
    asm volatile(
        "{\n\t.reg .pred p;\n\t"
        "mbarrier.try_wait.parity.acquire.cta.shared::cta.b64 p, [%1], %2;\n\t"
        "selp.b32 %0, 1, 0, p;\n\t}"
        : "=r"(done) : "r"(bar), "r"(parity) : "memory");
    while (!done) {
        asm volatile(
            "{\n\t.reg .pred p;\n\t"
            "mbarrier.try_wait.parity.acquire.cta.shared::cta.b64 p, [%1], %2, 0x989680;\n\t"
            "selp.b32 %0, 1, 0, p;\n\t}"
            : "=r"(done) : "r"(bar), "r"(parity) : "memory");
    }
}

__device__ __forceinline__ void bulk_g2s(uint32_t dst, const void* src,
                                         uint32_t bytes, uint32_t bar) {
    asm volatile(
        "cp.async.bulk.shared::cluster.global.mbarrier::complete_tx::bytes "
        "[%0], [%1], %2, [%3];"
        :: "r"(dst), "l"(src), "r"(bytes), "r"(bar) : "memory");
}

// ============================ prep kernels ============================

// Fused front kernel: blocks [0, TR_BLOCKS) transpose x into g_xT;
// blocks [TR_BLOCKS, TR_BLOCKS+SC_BLOCKS) scatter thresholds by feature.
// g_fcount is zeroed by a cudaMemsetAsync BEFORE this kernel (stream order).
__global__ void __launch_bounds__(SC_TPB, 2)
prep_front_kernel(const float* __restrict__ x,
                  const int*   __restrict__ features,
                  const float* __restrict__ thresholds)
{
    const int blk = blockIdx.x;
    const int tid = threadIdx.x;

    if (blk < TR_BLOCKS) {
        // ---- transpose tile ----
        __shared__ float t[32][33];
        const int tx = tid & 31;
        const int ty = tid >> 5;              // 0..7
        const int sBase = (blk >> 2) * 32;    // 1024 sample tiles
        const int fBase = (blk & 3) * 32;     // 4 feature tiles

        #pragma unroll
        for (int rr = ty; rr < 32; rr += 8)
            t[rr][tx] = x[(size_t)(sBase + rr) * NFEAT + fBase + tx];
        __syncthreads();
        #pragma unroll
        for (int rr = ty; rr < 32; rr += 8)
            g_xT[(size_t)(fBase + rr) * BATCH + sBase + tx] = t[tx][rr];
    } else {
        // ---- scatter block ----
        __shared__ int h[NFEAT];
        __shared__ int hbase[NFEAT];
        const int sblk = blk - TR_BLOCKS;

        for (int i = tid; i < NFEAT; i += SC_TPB) h[i] = 0;
        __syncthreads();

        int      fv[SC_PER_TH];
        uint32_t kv[SC_PER_TH];
        const int base = sblk * (SC_TPB * SC_PER_TH);

        #pragma unroll
        for (int e = 0; e < SC_PER_TH; e++) {
            int i = base + e * SC_TPB + tid;
            fv[e] = -1;
            if (i < NELEMS) {
                fv[e] = features[i];
                kv[e] = fkey(thresholds[i] + 0.0f);
                atomicAdd(&h[fv[e]], 1);
            }
        }
        __syncthreads();

        for (int i = tid; i < NFEAT; i += SC_TPB) {
            hbase[i] = atomicAdd(&g_fcount[i], h[i]);
            h[i] = 0;
        }
        __syncthreads();

        #pragma unroll
        for (int e = 0; e < SC_PER_TH; e++) {
            if (fv[e] >= 0) {
                int i   = base + e * SC_TPB + tid;
                int off = hbase[fv[e]] + atomicAdd(&h[fv[e]], 1);
                g_tpair[(size_t)fv[e] * FSEG + off] =
                    ((uint64_t)kv[e] << 32) | (uint32_t)i;
            }
        }
    }
}

__global__ void __launch_bounds__(1024, 1)
prep_sort_kernel()
{
    extern __shared__ char sm4[];
    uint32_t* skey = reinterpret_cast<uint32_t*>(sm4);

    const int f    = blockIdx.x;
    const int tid  = threadIdx.x;
    const int lane = tid & 31;
    const int m    = g_fcount[f];
    const uint64_t* seg = g_tpair + (size_t)f * FSEG;
    const uint32_t prefix = (uint32_t)(f * SPC) << 12;

    for (int p = tid; p < SORTN; p += 1024)
        skey[p] = (p < m) ? (uint32_t)(seg[p] >> 32) : 0xFFFFFFFFu;
    __syncthreads();

    uint32_t v[4];

    auto warp_phase = [&](int jj, int k) {
        if (jj >= 4) {
            const int lm = jj >> 2;
            #pragma unroll
            for (int e = 0; e < 4; e++) {
                uint32_t o = __shfl_xor_sync(0xffffffffu, v[e], lm);
                int  i     = (tid << 2) + e;
                bool up    = ((i & k) == 0);
                bool lower = ((lane & lm) == 0);
                uint32_t mn = min(v[e], o), mx = max(v[e], o);
                v[e] = (lower == up) ? mn : mx;
            }
        } else {
            #pragma unroll
            for (int e = 0; e < 4; e++) {
                int pe = e ^ jj;
                if (pe > e) {
                    int  i  = (tid << 2) + e;
                    bool up = ((i & k) == 0);
                    uint32_t a = v[e], b = v[pe];
                    if ((a > b) == up) { v[e] = b; v[pe] = a; }
                }
            }
        }
    };

    #pragma unroll
    for (int e = 0; e < 4; e++) v[e] = skey[(tid << 2) + e];
    for (int k = 2; k <= 128; k <<= 1)
        for (int jj = k >> 1; jj >= 1; jj >>= 1)
            warp_phase(jj, k);
    #pragma unroll
    for (int e = 0; e < 4; e++) skey[(tid << 2) + e] = v[e];
    __syncthreads();

    for (int k = 256; k <= SORTN; k <<= 1) {
        for (int jj = k >> 1; jj >= 128; jj >>= 1) {
            for (int i = tid; i < SORTN; i += 1024) {
                int p = i ^ jj;
                if (p > i) {
                    uint32_t a = skey[i], b = skey[p];
                    bool up = ((i & k) == 0);
                    if ((a > b) == up) { skey[i] = b; skey[p] = a; }
                }
            }
            __syncthreads();
        }
        #pragma unroll
        for (int e = 0; e < 4; e++) v[e] = skey[(tid << 2) + e];
        for (int jj = 64; jj >= 1; jj >>= 1)
            warp_phase(jj, k);
        #pragma unroll
        for (int e = 0; e < 4; e++) skey[(tid << 2) + e] = v[e];
        __syncthreads();
    }

    for (int p = tid; p < m; p += 1024) {
        uint64_t pr  = seg[p];
        uint32_t key = (uint32_t)(pr >> 32);
        uint32_t id  = (uint32_t)(pr & 0xFFFFFFFFull);
        int pos = 0;
        #pragma unroll
        for (int w = SORTN >> 1; w >= 1; w >>= 1)
            if (skey[pos + w - 1] <= key) pos += w;
        g_nodesQ[id] = prefix | (uint32_t)pos;
    }

    for (int p = tid; p < SORTN; p += 1024)
        g_skey[(size_t)f * SORTN + p] = skey[p];
}

__global__ void __launch_bounds__(1024, 1)
prep_xcode_kernel()
{
    extern __shared__ char sm4[];
    uint32_t* skey = reinterpret_cast<uint32_t*>(sm4);
    uint32_t* rep  = reinterpret_cast<uint32_t*>(sm4 + SORTN * 4);

    const int f    = blockIdx.x >> 2;
    const int part = blockIdx.x & 3;
    const int tid  = threadIdx.x;
    const int lane = tid & 31;

    for (int p = tid; p < SORTN; p += 1024)
        skey[p] = g_skey[(size_t)f * SORTN + p];
    __syncthreads();

    for (int i = tid; i < REP_NODES * 32; i += 1024) {
        int nb = i >> 5;
        int L  = 31 - __clz(nb + 1);
        int q  = (nb + 1) - (1 << L);
        int w  = 2048 >> L;
        rep[i] = skey[(2 * q + 1) * w - 1];
    }
    __syncthreads();

    const int sBase = part * XCODE_SAMP;
    uint32_t key[XCODE_ILP];
    int      qn [XCODE_ILP];

    #pragma unroll
    for (int i = 0; i < XCODE_ILP; i++) {
        int s  = sBase + i * 1024 + tid;
        key[i] = fkey(g_xT[(size_t)f * BATCH + s] + 0.0f);
        qn[i]  = 0;
    }
    #pragma unroll
    for (int L = 0; L < 9; L++) {
        #pragma unroll
        for (int i = 0; i < XCODE_ILP; i++) {
            uint32_t tk = rep[(((1 << L) - 1 + qn[i]) << 5) + lane];
            qn[i] = 2 * qn[i] + (tk < key[i]);
        }
    }
    #pragma unroll
    for (int i = 0; i < XCODE_ILP; i++) qn[i] <<= 3;
    {
        #pragma unroll
        for (int i = 0; i < XCODE_ILP; i++)
            if (skey[qn[i] + 3] < key[i]) qn[i] += 4;
        #pragma unroll
        for (int i = 0; i < XCODE_ILP; i++)
            if (skey[qn[i] + 1] < key[i]) qn[i] += 2;
        #pragma unroll
        for (int i = 0; i < XCODE_ILP; i++)
            if (skey[qn[i]] < key[i]) qn[i] += 1;
    }
    // 12-bit code stored as u16 (prefix re-applied during main staging)
    #pragma unroll
    for (int i = 0; i < XCODE_ILP; i++) {
        int s = sBase + i * 1024 + tid;
        g_xcode[(size_t)f * BATCH + s] = (uint16_t)qn[i];
    }
}

// ============================ main kernel ============================

__global__ void __launch_bounds__(TPB, 2)
gbt_forest_kernel(const float* __restrict__ leaf_values,
                  const float* __restrict__ init_out,
                  float*       __restrict__ out)
{
    uint32_t* xsw = reinterpret_cast<uint32_t*>(smem_raw);
    uint64_t* mbar = reinterpret_cast<uint64_t*>(smem_raw + MBAR_OFF);

    const int tid  = threadIdx.x;
    const int lane = tid & 31;
    const int q    = tid / SPC;
    const int r    = tid - q * SPC;
    const int base = blockIdx.x * SPC;

    const uint32_t full0  = s2u(&mbar[0]);
    const uint32_t full1  = s2u(&mbar[1]);
    const uint32_t empty0 = s2u(&mbar[2]);
    const uint32_t empty1 = s2u(&mbar[3]);
    const uint32_t dst0   = s2u(smem_raw + BUF_OFF(0));
    const uint32_t dst1   = s2u(smem_raw + BUF_OFF(1));

    const uint32_t* gN = g_nodesQ;

    if (tid == 0) {
        mbar_init(full0, 1);
        mbar_init(full1, 1);
        mbar_init(empty0, NWARPS);
        mbar_init(empty1, NWARPS);
        asm volatile("fence.proxy.async.shared::cta;" ::: "memory");
        mbar_expect_tx(full0, BUF_BYTES);
        bulk_g2s(dst0,              gN,                       NODE_BYTES, full0);
        bulk_g2s(dst0 + NODE_BYTES, leaf_values,              LEAF_BYTES, full0);
        mbar_expect_tx(full1, BUF_BYTES);
        bulk_g2s(dst1,              gN + NODE_CHUNK,          NODE_BYTES, full1);
        bulk_g2s(dst1 + NODE_BYTES, leaf_values + LEAF_CHUNK, LEAF_BYTES, full1);
    }

    // Stage x-code tile: u16 global code -> u32 prefixed smem word
    for (int ii = tid; ii < NFEAT * SPC; ii += TPB) {
        int ff = ii / SPC;
        int rr = ii - ff * SPC;
        int gs = min(base + rr, BATCH - 1);
        uint32_t code = g_xcode[(size_t)ff * BATCH + gs];
        xsw[ff * SPC + rr] = ((uint32_t)(ff * SPC) << 12) | code;
    }
    __syncthreads();

    float acc[NCLS];
    #pragma unroll
    for (int k = 0; k < NCLS; k++) acc[k] = 0.0f;

    const uint32_t* xcol = xsw + r;

    for (int c = 0; c < NCHUNK; c++) {
        const int b  = c & 1;
        const int ph = (c >> 1) & 1;
        const uint32_t fullB  = b ? full1 : full0;
        const uint32_t emptyB = b ? empty1 : empty0;
        const char* pCur = smem_raw + BUF_OFF(b);

        mbar_wait(fullB, ph);

        const uint32_t* nodeB = reinterpret_cast<const uint32_t*>(pCur);
        const float*    leafB = reinterpret_cast<const float*>(pCur + NODE_BYTES);

        #pragma unroll
        for (int g = 0; g < 2; g++) {
            const int tjb = q * NCLS + g * 5;
            const uint32_t* nt0 = nodeB + tjb * NINT;
            const uint32_t* nt1 = nt0 + NINT;
            const uint32_t* nt2 = nt1 + NINT;
            const uint32_t* nt3 = nt2 + NINT;
            const uint32_t* nt4 = nt3 + NINT;
            uint32_t i0 = 0, i1 = 0, i2 = 0, i3 = 0, i4 = 0;
            #pragma unroll
            for (int l = 0; l < 6; l++) {
                uint32_t n0 = nt0[i0];
                uint32_t n1 = nt1[i1];
                uint32_t n2 = nt2[i2];
                uint32_t n3 = nt3[i3];
                uint32_t n4 = nt4[i4];
                uint32_t c0 = xcol[n0 >> 12];
                uint32_t c1 = xcol[n1 >> 12];
                uint32_t c2 = xcol[n2 >> 12];
                uint32_t c3 = xcol[n3 >> 12];
                uint32_t c4 = xcol[n4 >> 12];
                i0 = 2 * i0 + 1 + (c0 >= n0);
                i1 = 2 * i1 + 1 + (c1 >= n1);
                i2 = 2 * i2 + 1 + (c2 >= n2);
                i3 = 2 * i3 + 1 + (c3 >= n3);
                i4 = 2 * i4 + 1 + (c4 >= n4);
            }
            acc[g * 5 + 0] += leafB[(tjb + 0) * NLEAF + ((int)i0 - NINT)];
            acc[g * 5 + 1] += leafB[(tjb + 1) * NLEAF + ((int)i1 - NINT)];
            acc[g * 5 + 2] += leafB[(tjb + 2) * NLEAF + ((int)i2 - NINT)];
            acc[g * 5 + 3] += leafB[(tjb + 3) * NLEAF + ((int)i3 - NINT)];
            acc[g * 5 + 4] += leafB[(tjb + 4) * NLEAF + ((int)i4 - NINT)];
        }

        __syncwarp();
        if (lane == 0) mbar_arrive(emptyB);

        if (tid == 0 && c + 2 < NCHUNK) {
            mbar_wait(emptyB, ph);
            asm volatile("fence.proxy.async.shared::cta;" ::: "memory");
            const int nc = c + 2;
            const uint32_t dstB = b ? dst1 : dst0;
            mbar_expect_tx(fullB, BUF_BYTES);
            bulk_g2s(dstB,              gN + (size_t)nc * NODE_CHUNK, NODE_BYTES, fullB);
            bulk_g2s(dstB + NODE_BYTES, leaf_values + (size_t)nc * LEAF_CHUNK,
                     LEAF_BYTES, fullB);
        }
    }

    __syncthreads();

    float* red = reinterpret_cast<float*>(smem_raw);
    if (q > 0) {
        #pragma unroll
        for (int k = 0; k < NCLS; k++)
            red[((q - 1) * SPC + r) * NCLS + k] = acc[k];
    }
    __syncthreads();

    if (q == 0 && base + r < BATCH) {
        const int sample = base + r;
        #pragma unroll
        for (int k = 0; k < NCLS; k++) {
            float v = acc[k]
                    + red[(0 * SPC + r) * NCLS + k]
                    + red[(1 * SPC + r) * NCLS + k]
                    + red[(2 * SPC + r) * NCLS + k];
            out[(size_t)sample * NCLS + k] = __ldg(init_out + k) + LR * v;
        }
    }
}

extern "C" void kernel_launch(void* const* d_in, const int* in_sizes, int n_in,
                              void* d_out, int out_size)
{
    (void)in_sizes; (void)n_in; (void)out_size;

    const float* x           = (const float*)d_in[0];
    const int*   features    = (const int*)  d_in[1];
    const float* thresholds  = (const float*)d_in[2];
    const float* leaf_values = (const float*)d_in[3];
    const float* init_out    = (const float*)d_in[4];
    float*       out         = (float*)d_out;

    static bool attr_set = false;
    static void* d_fcount = nullptr;
    if (!attr_set) {
        cudaFuncSetAttribute(gbt_forest_kernel,
                             cudaFuncAttributeMaxDynamicSharedMemorySize, SMEM_TOTAL);
        cudaFuncSetAttribute(prep_sort_kernel,
                             cudaFuncAttributeMaxDynamicSharedMemorySize, SORT_SMEM);
        cudaFuncSetAttribute(prep_xcode_kernel,
                             cudaFuncAttributeMaxDynamicSharedMemorySize, XCODE_SMEM);
        cudaGetSymbolAddress(&d_fcount, g_fcount);
        attr_set = true;
    }

    cudaMemsetAsync(d_fcount, 0, NFEAT * sizeof(int));   // graph memset node
    prep_front_kernel<<<TR_BLOCKS + SC_BLOCKS, SC_TPB>>>(x, features, thresholds);
    prep_sort_kernel<<<NFEAT, 1024, SORT_SMEM>>>();
    prep_xcode_kernel<<<NFEAT * XCODE_SPLIT, 1024, XCODE_SMEM>>>();
    gbt_forest_kernel<<<GRID, TPB, SMEM_TOTAL>>>(leaf_values, init_out, out);
}